// round 2
// baseline (speedup 1.0000x reference)
#include <cuda_runtime.h>
#include <cuda_bf16.h>
#include <cstdint>

// ---------------------------------------------------------------------------
// MentionPrunerSpanBert: B=4, T=512, L=15, D=2048, H=1024, K=205
// Pipeline: 2x GEMM+ReLU -> GEMV score + mask penalty -> per-batch top-K
//           -> sort indices -> gathers -> square/triangular masks
// Output layout (float32, concatenated flattened, reference return order):
//   prune_scores[30720], top_idx[820], f_vecs[1679360], f_scores[820],
//   f_begin[820], f_end[820], span_lengths[4], square_mask[168100],
//   triangular_mask[168100]   -> total 2,049,564
// ---------------------------------------------------------------------------

#define BB   4
#define TT   512
#define LL   15
#define DD   2048
#define HH   1024
#define KK   205
#define TL   (TT * LL)          // 7680
#define MM   (BB * TL)          // 30720

#define O_PSCORE 0
#define O_TOPIDX (O_PSCORE + MM)                      // 30720
#define O_FVECS  (O_TOPIDX + BB * KK)                 // 31540
#define O_FSCORE (O_FVECS  + (size_t)BB * KK * DD)    // 1710900
#define O_FBEGIN (O_FSCORE + BB * KK)                 // 1711720
#define O_FEND   (O_FBEGIN + BB * KK)                 // 1712540
#define O_SPLEN  (O_FEND   + BB * KK)                 // 1713360
#define O_SQMASK (O_SPLEN  + BB)                      // 1713364
#define O_TRMASK (O_SQMASK + BB * KK * KK)            // 1881464

// Scratch (device globals; no allocation allowed)
__device__ float g_h1[(size_t)MM * HH];   // 125.8 MB
__device__ float g_h2[(size_t)MM * HH];   // 125.8 MB
__device__ int   g_topidx[BB * KK];
__device__ int   g_spanlen[BB];

// ---------------------------------------------------------------------------
// Tiled SGEMM with fused bias + ReLU.  C[M,N] = relu(A[M,K] @ B[K,N] + bias)
// BM=128, BN=128, BK=16, 256 threads, 8x8 per-thread microtile.
// M, N, K all multiples of tile dims for our shapes (no bounds checks).
// ---------------------------------------------------------------------------
#define GBM 128
#define GBN 128
#define GBK 16

__global__ __launch_bounds__(256, 2)
void sgemm_bias_relu(const float* __restrict__ A, const float* __restrict__ B,
                     const float* __restrict__ bias, float* __restrict__ C,
                     int M, int N, int Kd)
{
    __shared__ float As[GBK][GBM + 4];   // padded to dodge store conflicts
    __shared__ float Bs[GBK][GBN];

    const int t  = threadIdx.x;
    const int tx = t & 15;         // 0..15 -> column group
    const int ty = t >> 4;         // 0..15 -> row group
    const int mBase = blockIdx.y * GBM;
    const int nBase = blockIdx.x * GBN;

    float acc[8][8];
#pragma unroll
    for (int i = 0; i < 8; i++)
#pragma unroll
        for (int j = 0; j < 8; j++) acc[i][j] = 0.0f;

    for (int k0 = 0; k0 < Kd; k0 += GBK) {
        // Load A tile: 128 rows x 16 cols = 512 float4, 2 per thread; store transposed
#pragma unroll
        for (int p = 0; p < 2; p++) {
            int idx = t + p * 256;
            int row = idx >> 2;
            int c4  = idx & 3;
            float4 v = *(const float4*)(A + (size_t)(mBase + row) * Kd + k0 + c4 * 4);
            As[c4 * 4 + 0][row] = v.x;
            As[c4 * 4 + 1][row] = v.y;
            As[c4 * 4 + 2][row] = v.z;
            As[c4 * 4 + 3][row] = v.w;
        }
        // Load B tile: 16 rows x 128 cols = 512 float4, 2 per thread
#pragma unroll
        for (int p = 0; p < 2; p++) {
            int idx = t + p * 256;
            int row = idx >> 5;
            int c4  = idx & 31;
            float4 v = *(const float4*)(B + (size_t)(k0 + row) * N + nBase + c4 * 4);
            *(float4*)&Bs[row][c4 * 4] = v;
        }
        __syncthreads();

#pragma unroll
        for (int kk = 0; kk < GBK; kk++) {
            float ar[8], br[8];
#pragma unroll
            for (int i = 0; i < 8; i++) ar[i] = As[kk][ty * 8 + i];
#pragma unroll
            for (int j = 0; j < 8; j++) br[j] = Bs[kk][tx * 8 + j];
#pragma unroll
            for (int i = 0; i < 8; i++)
#pragma unroll
                for (int j = 0; j < 8; j++)
                    acc[i][j] = fmaf(ar[i], br[j], acc[i][j]);
        }
        __syncthreads();
    }

#pragma unroll
    for (int i = 0; i < 8; i++) {
        int row = mBase + ty * 8 + i;
#pragma unroll
        for (int j = 0; j < 8; j++) {
            int col = nBase + tx * 8 + j;
            float v = acc[i][j] + bias[col];
            C[(size_t)row * N + col] = v > 0.0f ? v : 0.0f;
        }
    }
}

// ---------------------------------------------------------------------------
// GEMV: scores = H2 @ W3 + b3, then penalty -> prune_scores (written to d_out)
// One warp per row; 8 warps per block.
// ---------------------------------------------------------------------------
__global__ void score_kernel(const float* __restrict__ h2,
                             const float* __restrict__ W3,
                             const float* __restrict__ b3,
                             const float* __restrict__ mask,
                             float* __restrict__ out)
{
    int row  = blockIdx.x * 8 + (threadIdx.x >> 5);
    int lane = threadIdx.x & 31;
    const float* hrow = h2 + (size_t)row * HH;
    float s = 0.0f;
#pragma unroll
    for (int i = 0; i < 8; i++) {
        float4 hv = *(const float4*)(hrow + lane * 4 + i * 128);
        float4 wv = *(const float4*)(W3   + lane * 4 + i * 128);
        s += hv.x * wv.x + hv.y * wv.y + hv.z * wv.z + hv.w * wv.w;
    }
#pragma unroll
    for (int o = 16; o; o >>= 1) s += __shfl_xor_sync(0xffffffffu, s, o);
    if (lane == 0) {
        float p = s + b3[0] - (1.0f - mask[row]) * 10000.0f;
        out[O_PSCORE + row] = p;
    }
}

// ---------------------------------------------------------------------------
// Per-batch top-K + index sort. One block per batch, 1024 threads.
// 64-bit composite key: (~ord(score)) << 32 | idx  -> ascending sort gives
// descending score, ties broken by ascending index (matches lax.top_k).
// ---------------------------------------------------------------------------
__global__ void topk_kernel(const float* __restrict__ out_ro,  // d_out (scores region)
                            const int* __restrict__ seqlen,
                            float* __restrict__ out,
                            int* __restrict__ topidx,
                            int* __restrict__ splen)
{
    extern __shared__ unsigned long long key[];   // 8192 * 8 = 64 KB
    const int b = blockIdx.x;
    const int t = threadIdx.x;

    for (int i = t; i < 8192; i += 1024) {
        unsigned long long kv;
        if (i < TL) {
            float s = out_ro[O_PSCORE + b * TL + i];
            unsigned u = __float_as_uint(s);
            u = (u & 0x80000000u) ? ~u : (u | 0x80000000u);   // ascending-ordered map
            kv = ((unsigned long long)(~u) << 32) | (unsigned)i;
        } else {
            kv = 0xFFFFFFFFFFFFFFFFull;
        }
        key[i] = kv;
    }
    __syncthreads();

    for (int k = 2; k <= 8192; k <<= 1) {
        for (int j = k >> 1; j > 0; j >>= 1) {
            for (int i = t; i < 8192; i += 1024) {
                int ixj = i ^ j;
                if (ixj > i) {
                    unsigned long long a = key[i], c = key[ixj];
                    bool up = ((i & k) == 0);
                    if ((a > c) == up) { key[i] = c; key[ixj] = a; }
                }
            }
            __syncthreads();
        }
    }

    // Extract top-205 indices, sort ascending (pad with INT_MAX)
    __shared__ int sidx[256];
    if (t < 256) sidx[t] = (t < KK) ? (int)(key[t] & 0xFFFFFFFFull) : 0x7FFFFFFF;
    __syncthreads();
    for (int k = 2; k <= 256; k <<= 1) {
        for (int j = k >> 1; j > 0; j >>= 1) {
            if (t < 256) {
                int i = t, ixj = i ^ j;
                if (ixj > i) {
                    int a = sidx[i], c = sidx[ixj];
                    bool up = ((i & k) == 0);
                    if ((a > c) == up) { sidx[i] = c; sidx[ixj] = a; }
                }
            }
            __syncthreads();
        }
    }

    if (t < KK) {
        topidx[b * KK + t] = sidx[t];
        out[O_TOPIDX + b * KK + t] = (float)sidx[t];
    }
    if (t == 0) {
        int len = (int)ceilf((float)seqlen[b] * 0.4f);
        splen[b] = len;
        out[O_SPLEN + b] = (float)len;
    }
}

// ---------------------------------------------------------------------------
// Gather f_vecs / f_scores / f_begin / f_end. One block per (b,k).
// ---------------------------------------------------------------------------
__global__ void gather_kernel(const float* __restrict__ span_vecs,
                              const int* __restrict__ span_begin,
                              const int* __restrict__ span_end,
                              const int* __restrict__ topidx,
                              float* __restrict__ out)
{
    int blk = blockIdx.x;
    int b = blk / KK, k = blk % KK;
    int idx = topidx[b * KK + k];
    const float* src = span_vecs + ((size_t)b * TL + idx) * DD;
    float* dst = out + O_FVECS + ((size_t)b * KK + k) * DD;
    for (int i = threadIdx.x; i < DD; i += 256) dst[i] = src[i];
    if (threadIdx.x == 0) {
        int g = b * TL + idx;
        out[O_FSCORE + b * KK + k] = out[O_PSCORE + g];
        out[O_FBEGIN + b * KK + k] = (float)span_begin[g];
        out[O_FEND   + b * KK + k] = (float)span_end[g];
    }
}

// ---------------------------------------------------------------------------
// square_mask + triangular_mask
// ---------------------------------------------------------------------------
__global__ void mask_kernel(const int* __restrict__ splen, float* __restrict__ out)
{
    int i = blockIdx.x * blockDim.x + threadIdx.x;
    const int per = KK * KK;                 // 42025
    if (i >= BB * per) return;
    int b = i / per, r = i % per;
    int ii = r / KK, jj = r % KK;
    int len = splen[b];
    float v = (ii < len && jj < len) ? 1.0f : 0.0f;
    out[O_SQMASK + i] = v;
    out[O_TRMASK + i] = (jj <= ii) ? v : 0.0f;
}

// ---------------------------------------------------------------------------
extern "C" void kernel_launch(void* const* d_in, const int* in_sizes, int n_in,
                              void* d_out, int out_size)
{
    const float* span_vecs  = (const float*)d_in[0];
    const float* span_mask  = (const float*)d_in[1];
    const int*   span_begin = (const int*)  d_in[2];
    const int*   span_end   = (const int*)  d_in[3];
    const int*   seqlen     = (const int*)  d_in[4];
    const float* W1 = (const float*)d_in[5];
    const float* b1 = (const float*)d_in[6];
    const float* W2 = (const float*)d_in[7];
    const float* b2 = (const float*)d_in[8];
    const float* W3 = (const float*)d_in[9];
    const float* b3 = (const float*)d_in[10];
    float* out = (float*)d_out;

    float* h1 = nullptr; float* h2 = nullptr;
    cudaGetSymbolAddress((void**)&h1, g_h1);
    cudaGetSymbolAddress((void**)&h2, g_h2);
    int* topidx = nullptr; int* splen = nullptr;
    cudaGetSymbolAddress((void**)&topidx, g_topidx);
    cudaGetSymbolAddress((void**)&splen, g_spanlen);

    // GEMM1: [30720,2048] x [2048,1024] + b1, ReLU
    {
        dim3 grid(HH / GBN, MM / GBM);   // (8, 240)
        sgemm_bias_relu<<<grid, 256>>>(span_vecs, W1, b1, h1, MM, HH, DD);
    }
    // GEMM2: [30720,1024] x [1024,1024] + b2, ReLU
    {
        dim3 grid(HH / GBN, MM / GBM);
        sgemm_bias_relu<<<grid, 256>>>(h1, W2, b2, h2, MM, HH, HH);
    }
    // Scores + penalty -> prune_scores region of d_out
    score_kernel<<<MM / 8, 256>>>(h2, W3, b3, span_mask, out);

    // Top-K per batch (needs 64KB dynamic smem)
    cudaFuncSetAttribute(topk_kernel, cudaFuncAttributeMaxDynamicSharedMemorySize, 65536);
    topk_kernel<<<BB, 1024, 65536>>>(out, seqlen, out, topidx, splen);

    // Gathers
    gather_kernel<<<BB * KK, 256>>>(span_vecs, span_begin, span_end, topidx, out);

    // Masks
    {
        int n = BB * KK * KK;
        mask_kernel<<<(n + 255) / 256, 256>>>(splen, out);
    }
}

// round 4
// speedup vs baseline: 2.2403x; 2.2403x over previous
#include <cuda_runtime.h>
#include <cuda_bf16.h>
#include <cstdint>

// ---------------------------------------------------------------------------
// MentionPrunerSpanBert: B=4, T=512, L=15, D=2048, H=1024, K=205
// R3: tcgen05 unavailable (harness compiles via compute_103, arch-specific
//     features rejected). Use arch-agnostic mma.sync (HMMA) bf16 with hi/lo
//     split precision (3 terms) -> fp32-grade accuracy, tensor-core speed.
// ---------------------------------------------------------------------------

#define BB   4
#define TT   512
#define LL   15
#define DD   2048
#define HH   1024
#define KK   205
#define TL   (TT * LL)          // 7680
#define MM   (BB * TL)          // 30720

#define O_PSCORE 0
#define O_TOPIDX (O_PSCORE + MM)
#define O_FVECS  (O_TOPIDX + BB * KK)
#define O_FSCORE (O_FVECS  + (size_t)BB * KK * DD)
#define O_FBEGIN (O_FSCORE + BB * KK)
#define O_FEND   (O_FBEGIN + BB * KK)
#define O_SPLEN  (O_FEND   + BB * KK)
#define O_SQMASK (O_SPLEN  + BB)
#define O_TRMASK (O_SQMASK + BB * KK * KK)

// ---------------- device scratch (no allocations allowed) -------------------
__device__ __nv_bfloat16 g_xhi[(size_t)MM * DD];
__device__ __nv_bfloat16 g_xlo[(size_t)MM * DD];
__device__ __nv_bfloat16 g_h1hi[(size_t)MM * HH];
__device__ __nv_bfloat16 g_h1lo[(size_t)MM * HH];
__device__ __nv_bfloat16 g_w1thi[(size_t)HH * DD];
__device__ __nv_bfloat16 g_w1tlo[(size_t)HH * DD];
__device__ __nv_bfloat16 g_w2thi[(size_t)HH * HH];
__device__ __nv_bfloat16 g_w2tlo[(size_t)HH * HH];
__device__ float g_h2[(size_t)MM * HH];
__device__ int   g_topidx[BB * KK];
__device__ int   g_spanlen[BB];

// ---------------- PTX helpers (all arch-agnostic, sm_80+) -------------------
__device__ __forceinline__ uint32_t smem_u32_of(const void* p) {
    uint32_t a;
    asm("{ .reg .u64 t; cvta.to.shared.u64 t, %1; cvt.u32.u64 %0, t; }" : "=r"(a) : "l"(p));
    return a;
}
#define CP16(dst, src) \
    asm volatile("cp.async.cg.shared.global [%0], [%1], 16;" :: "r"((uint32_t)(dst)), "l"(src))
#define CP_COMMIT() asm volatile("cp.async.commit_group;" ::: "memory")
#define CP_WAIT(n)  asm volatile("cp.async.wait_group %0;" :: "n"(n) : "memory")

#define LDSM_X4(R0, R1, R2, R3, addr) \
    asm volatile("ldmatrix.sync.aligned.m8n8.x4.shared.b16 {%0,%1,%2,%3}, [%4];" \
        : "=r"(R0), "=r"(R1), "=r"(R2), "=r"(R3) : "r"(addr))

#define MMA_BF16(D, A, B0, B1) \
    asm volatile("mma.sync.aligned.m16n8k16.row.col.f32.bf16.bf16.f32 " \
        "{%0,%1,%2,%3}, {%4,%5,%6,%7}, {%8,%9}, {%0,%1,%2,%3};" \
        : "+f"((D)[0]), "+f"((D)[1]), "+f"((D)[2]), "+f"((D)[3]) \
        : "r"((A)[0]), "r"((A)[1]), "r"((A)[2]), "r"((A)[3]), "r"(B0), "r"(B1))

// ---------------------------------------------------------------------------
// Split / transpose-split preprocessing
// ---------------------------------------------------------------------------
__global__ void split_kernel(const float4* __restrict__ x,
                             __nv_bfloat16* __restrict__ hi,
                             __nv_bfloat16* __restrict__ lo, size_t n4)
{
    size_t i = (size_t)blockIdx.x * blockDim.x + threadIdx.x;
    if (i >= n4) return;
    float4 v = x[i];
    float vv[4] = {v.x, v.y, v.z, v.w};
    __nv_bfloat16 h[4], l[4];
#pragma unroll
    for (int k = 0; k < 4; k++) {
        h[k] = __float2bfloat16(vv[k]);
        l[k] = __float2bfloat16(vv[k] - __bfloat162float(h[k]));
    }
    __nv_bfloat162 h01, h23, l01, l23;
    h01.x = h[0]; h01.y = h[1]; h23.x = h[2]; h23.y = h[3];
    l01.x = l[0]; l01.y = l[1]; l23.x = l[2]; l23.y = l[3];
    __nv_bfloat162* hp = reinterpret_cast<__nv_bfloat162*>(hi) + 2 * i;
    __nv_bfloat162* lp = reinterpret_cast<__nv_bfloat162*>(lo) + 2 * i;
    hp[0] = h01; hp[1] = h23;
    lp[0] = l01; lp[1] = l23;
}

// W [K,N] row-major -> WT [N,K] (K-major) split into hi/lo bf16
__global__ void transpose_split(const float* __restrict__ W,
                                __nv_bfloat16* __restrict__ Thi,
                                __nv_bfloat16* __restrict__ Tlo, int Kd, int N)
{
    size_t tid = (size_t)blockIdx.x * blockDim.x + threadIdx.x;
    if (tid >= (size_t)Kd * N) return;
    int k = (int)(tid % Kd);
    int n = (int)(tid / Kd);
    float v = W[(size_t)k * N + n];
    __nv_bfloat16 h = __float2bfloat16(v);
    Thi[tid] = h;
    Tlo[tid] = __float2bfloat16(v - __bfloat162float(h));
}

// ---------------------------------------------------------------------------
// Split-bf16 HMMA GEMM:  C[M,N] = relu((Ahi+Alo) @ (Bhi+Blo)^T + bias)
//   A: [M,K] bf16 hi/lo row-major. B: [N,K] bf16 hi/lo row-major (K-major).
//   Tile 128x128, BK=32, 256 threads (warps 4m x 2n, warp tile 32x64),
//   3-stage cp.async pipeline, ldmatrix fragments, 3 MMA terms per step.
//   OUT_SPLIT=1: write Chi/Clo bf16 (re-split).  OUT_SPLIT=0: write fp32 Cf.
// ---------------------------------------------------------------------------
#define GBM 128
#define GBN 128
#define GBK 32
#define ROWB 80                       // smem row stride bytes (32 bf16 + pad)
#define SM_AH 0
#define SM_AL (128 * ROWB)            // 10240
#define SM_BH (2 * 128 * ROWB)        // 20480
#define SM_BL (3 * 128 * ROWB)        // 30720
#define STAGE_SZ (4 * 128 * ROWB)     // 40960
#define NSTAGE 3
#define GEMM_SMEM (NSTAGE * STAGE_SZ) // 122880

template <int OUT_SPLIT>
__global__ __launch_bounds__(256, 1)
void gemm3_mma(const __nv_bfloat16* __restrict__ Ahi, const __nv_bfloat16* __restrict__ Alo,
               const __nv_bfloat16* __restrict__ Bhi, const __nv_bfloat16* __restrict__ Blo,
               const float* __restrict__ bias,
               float* __restrict__ Cf,
               __nv_bfloat16* __restrict__ Chi, __nv_bfloat16* __restrict__ Clo,
               int M, int N, int Kd)
{
    extern __shared__ char smem[];
    const uint32_t sb = smem_u32_of(smem);
    const int t = threadIdx.x;
    const int lane = t & 31;
    const int wid = t >> 5;
    const int wm = wid & 3;           // 0..3 -> 32-row band
    const int wn = wid >> 2;          // 0..1 -> 64-col band
    const int mBase = blockIdx.y * GBM;
    const int nBase = blockIdx.x * GBN;
    const int NC = Kd / GBK;

    float acc[2][8][4];
#pragma unroll
    for (int mi = 0; mi < 2; mi++)
#pragma unroll
        for (int ni = 0; ni < 8; ni++)
#pragma unroll
            for (int j = 0; j < 4; j++) acc[mi][ni][j] = 0.0f;

    // per-thread load coordinates: 512 16B-chunks per matrix, 2 per thread
    const int l_row = (t * 2) >> 2;       // rows advance every 2 threads... (idx=2t)
    // (we recompute inside the loop for clarity/correctness)

    // ---- stage loader ----
    auto load_stage = [&](int cidx, int buf) {
        const size_t ko = (size_t)cidx * GBK;
        const uint32_t stg = sb + buf * STAGE_SZ;
#pragma unroll
        for (int p = 0; p < 2; p++) {
            const int idx = t + p * 256;      // 0..511
            const int row = idx >> 2;         // 0..127
            const int c16 = idx & 3;          // 16B chunk in 64B row
            const uint32_t doff = row * ROWB + c16 * 16;
            const size_t aoff = (size_t)(mBase + row) * Kd + ko + c16 * 8;
            const size_t boff = (size_t)(nBase + row) * Kd + ko + c16 * 8;
            CP16(stg + SM_AH + doff, Ahi + aoff);
            CP16(stg + SM_AL + doff, Alo + aoff);
            CP16(stg + SM_BH + doff, Bhi + boff);
            CP16(stg + SM_BL + doff, Blo + boff);
        }
        CP_COMMIT();
    };

    // prologue: stages 0,1
    load_stage(0, 0);
    load_stage(1, 1);

    // fragment address components
    const int ar = lane & 15, ac = lane >> 4;        // A ldmatrix lanes
    const int br = lane & 7,  bblk = lane >> 3;      // B ldmatrix lanes

#pragma unroll 1
    for (int c = 0; c < NC; c++) {
        const int buf = c % NSTAGE;
        if (c < NC - 1) CP_WAIT(1); else CP_WAIT(0);
        __syncthreads();
        if (c + 2 < NC) load_stage(c + 2, (c + 2) % NSTAGE);

        const uint32_t stg = sb + buf * STAGE_SZ;
#pragma unroll
        for (int kk2 = 0; kk2 < 2; kk2++) {          // two k16 steps in BK=32
            const int kb = kk2 * 32;                 // byte offset of k16 block
            uint32_t ah[2][4], al[2][4];
#pragma unroll
            for (int mi = 0; mi < 2; mi++) {
                const uint32_t ra = (wm * 32 + mi * 16 + ar) * ROWB + kb + ac * 16;
                LDSM_X4(ah[mi][0], ah[mi][1], ah[mi][2], ah[mi][3], stg + SM_AH + ra);
                LDSM_X4(al[mi][0], al[mi][1], al[mi][2], al[mi][3], stg + SM_AL + ra);
            }
            uint32_t bh[8][2], bl[8][2];
#pragma unroll
            for (int nj = 0; nj < 4; nj++) {         // 2 n8-tiles per ldmatrix.x4
                const uint32_t rb = (wn * 64 + nj * 16 + (bblk >> 1) * 8 + br) * ROWB
                                    + kb + (bblk & 1) * 16;
                LDSM_X4(bh[2*nj][0], bh[2*nj][1], bh[2*nj+1][0], bh[2*nj+1][1], stg + SM_BH + rb);
                LDSM_X4(bl[2*nj][0], bl[2*nj][1], bl[2*nj+1][0], bl[2*nj+1][1], stg + SM_BL + rb);
            }
#pragma unroll
            for (int mi = 0; mi < 2; mi++)
#pragma unroll
                for (int ni = 0; ni < 8; ni++) {
                    MMA_BF16(acc[mi][ni], ah[mi], bh[ni][0], bh[ni][1]);
                    MMA_BF16(acc[mi][ni], ah[mi], bl[ni][0], bl[ni][1]);
                    MMA_BF16(acc[mi][ni], al[mi], bh[ni][0], bh[ni][1]);
                }
        }
    }

    // ---- epilogue: bias + relu (+ optional hi/lo re-split) ----
    const int r0 = lane >> 2;            // 0..7
    const int c0 = (lane & 3) << 1;      // 0,2,4,6
#pragma unroll
    for (int mi = 0; mi < 2; mi++) {
        const int rowA = mBase + wm * 32 + mi * 16 + r0;
#pragma unroll
        for (int ni = 0; ni < 8; ni++) {
            const int col = nBase + wn * 64 + ni * 8 + c0;
            const float bv0 = bias[col], bv1 = bias[col + 1];
            float v0 = acc[mi][ni][0] + bv0;  v0 = v0 > 0.0f ? v0 : 0.0f;
            float v1 = acc[mi][ni][1] + bv1;  v1 = v1 > 0.0f ? v1 : 0.0f;
            float v2 = acc[mi][ni][2] + bv0;  v2 = v2 > 0.0f ? v2 : 0.0f;
            float v3 = acc[mi][ni][3] + bv1;  v3 = v3 > 0.0f ? v3 : 0.0f;
            if (OUT_SPLIT) {
                __nv_bfloat16 h0 = __float2bfloat16(v0), h1 = __float2bfloat16(v1);
                __nv_bfloat16 h2 = __float2bfloat16(v2), h3 = __float2bfloat16(v3);
                __nv_bfloat162 hh, ll;
                hh.x = h0; hh.y = h1;
                ll.x = __float2bfloat16(v0 - __bfloat162float(h0));
                ll.y = __float2bfloat16(v1 - __bfloat162float(h1));
                *reinterpret_cast<__nv_bfloat162*>(Chi + (size_t)rowA * N + col) = hh;
                *reinterpret_cast<__nv_bfloat162*>(Clo + (size_t)rowA * N + col) = ll;
                hh.x = h2; hh.y = h3;
                ll.x = __float2bfloat16(v2 - __bfloat162float(h2));
                ll.y = __float2bfloat16(v3 - __bfloat162float(h3));
                *reinterpret_cast<__nv_bfloat162*>(Chi + (size_t)(rowA + 8) * N + col) = hh;
                *reinterpret_cast<__nv_bfloat162*>(Clo + (size_t)(rowA + 8) * N + col) = ll;
            } else {
                float2 w0; w0.x = v0; w0.y = v1;
                float2 w1; w1.x = v2; w1.y = v3;
                *reinterpret_cast<float2*>(Cf + (size_t)rowA * N + col) = w0;
                *reinterpret_cast<float2*>(Cf + (size_t)(rowA + 8) * N + col) = w1;
            }
        }
    }
}

// ---------------------------------------------------------------------------
// GEMV: scores = H2 @ W3 + b3, then penalty -> prune_scores (d_out)
// ---------------------------------------------------------------------------
__global__ void score_kernel(const float* __restrict__ h2,
                             const float* __restrict__ W3,
                             const float* __restrict__ b3,
                             const float* __restrict__ mask,
                             float* __restrict__ out)
{
    int row  = blockIdx.x * 8 + (threadIdx.x >> 5);
    int lane = threadIdx.x & 31;
    const float* hrow = h2 + (size_t)row * HH;
    float s = 0.0f;
#pragma unroll
    for (int i = 0; i < 8; i++) {
        float4 hv = *(const float4*)(hrow + lane * 4 + i * 128);
        float4 wv = *(const float4*)(W3   + lane * 4 + i * 128);
        s += hv.x * wv.x + hv.y * wv.y + hv.z * wv.z + hv.w * wv.w;
    }
#pragma unroll
    for (int o = 16; o; o >>= 1) s += __shfl_xor_sync(0xffffffffu, s, o);
    if (lane == 0) {
        out[O_PSCORE + row] = s + b3[0] - (1.0f - mask[row]) * 10000.0f;
    }
}

// ---------------------------------------------------------------------------
// Per-batch top-K (bitonic, proven in R1)
// ---------------------------------------------------------------------------
__global__ void topk_kernel(const float* __restrict__ out_ro,
                            const int* __restrict__ seqlen,
                            float* __restrict__ out,
                            int* __restrict__ topidx,
                            int* __restrict__ splen)
{
    extern __shared__ unsigned long long key[];
    const int b = blockIdx.x;
    const int t = threadIdx.x;

    for (int i = t; i < 8192; i += 1024) {
        unsigned long long kv;
        if (i < TL) {
            float s = out_ro[O_PSCORE + b * TL + i];
            unsigned u = __float_as_uint(s);
            u = (u & 0x80000000u) ? ~u : (u | 0x80000000u);
            kv = ((unsigned long long)(~u) << 32) | (unsigned)i;
        } else kv = 0xFFFFFFFFFFFFFFFFull;
        key[i] = kv;
    }
    __syncthreads();

    for (int k = 2; k <= 8192; k <<= 1)
        for (int j = k >> 1; j > 0; j >>= 1) {
            for (int i = t; i < 8192; i += 1024) {
                int ixj = i ^ j;
                if (ixj > i) {
                    unsigned long long a = key[i], c = key[ixj];
                    bool up = ((i & k) == 0);
                    if ((a > c) == up) { key[i] = c; key[ixj] = a; }
                }
            }
            __syncthreads();
        }

    __shared__ int sidx[256];
    if (t < 256) sidx[t] = (t < KK) ? (int)(key[t] & 0xFFFFFFFFull) : 0x7FFFFFFF;
    __syncthreads();
    for (int k = 2; k <= 256; k <<= 1)
        for (int j = k >> 1; j > 0; j >>= 1) {
            if (t < 256) {
                int i = t, ixj = i ^ j;
                if (ixj > i) {
                    int a = sidx[i], c = sidx[ixj];
                    bool up = ((i & k) == 0);
                    if ((a > c) == up) { sidx[i] = c; sidx[ixj] = a; }
                }
            }
            __syncthreads();
        }

    if (t < KK) {
        topidx[b * KK + t] = sidx[t];
        out[O_TOPIDX + b * KK + t] = (float)sidx[t];
    }
    if (t == 0) {
        int len = (int)ceilf((float)seqlen[b] * 0.4f);
        splen[b] = len;
        out[O_SPLEN + b] = (float)len;
    }
}

__global__ void gather_kernel(const float* __restrict__ span_vecs,
                              const int* __restrict__ span_begin,
                              const int* __restrict__ span_end,
                              const int* __restrict__ topidx,
                              float* __restrict__ out)
{
    int blk = blockIdx.x;
    int b = blk / KK, k = blk % KK;
    int idx = topidx[b * KK + k];
    const float* src = span_vecs + ((size_t)b * TL + idx) * DD;
    float* dst = out + O_FVECS + ((size_t)b * KK + k) * DD;
    for (int i = threadIdx.x; i < DD; i += 256) dst[i] = src[i];
    if (threadIdx.x == 0) {
        int g = b * TL + idx;
        out[O_FSCORE + b * KK + k] = out[O_PSCORE + g];
        out[O_FBEGIN + b * KK + k] = (float)span_begin[g];
        out[O_FEND   + b * KK + k] = (float)span_end[g];
    }
}

__global__ void mask_kernel(const int* __restrict__ splen, float* __restrict__ out)
{
    int i = blockIdx.x * blockDim.x + threadIdx.x;
    const int per = KK * KK;
    if (i >= BB * per) return;
    int b = i / per, r = i % per;
    int ii = r / KK, jj = r % KK;
    int len = splen[b];
    float v = (ii < len && jj < len) ? 1.0f : 0.0f;
    out[O_SQMASK + i] = v;
    out[O_TRMASK + i] = (jj <= ii) ? v : 0.0f;
}

// ---------------------------------------------------------------------------
extern "C" void kernel_launch(void* const* d_in, const int* in_sizes, int n_in,
                              void* d_out, int out_size)
{
    const float* span_vecs  = (const float*)d_in[0];
    const float* span_mask  = (const float*)d_in[1];
    const int*   span_begin = (const int*)  d_in[2];
    const int*   span_end   = (const int*)  d_in[3];
    const int*   seqlen     = (const int*)  d_in[4];
    const float* W1 = (const float*)d_in[5];
    const float* b1 = (const float*)d_in[6];
    const float* W2 = (const float*)d_in[7];
    const float* b2 = (const float*)d_in[8];
    const float* W3 = (const float*)d_in[9];
    const float* b3 = (const float*)d_in[10];
    float* out = (float*)d_out;

    __nv_bfloat16 *xhi, *xlo, *h1hi, *h1lo, *w1thi, *w1tlo, *w2thi, *w2tlo;
    float* h2; int *topidx, *splen;
    cudaGetSymbolAddress((void**)&xhi,   g_xhi);
    cudaGetSymbolAddress((void**)&xlo,   g_xlo);
    cudaGetSymbolAddress((void**)&h1hi,  g_h1hi);
    cudaGetSymbolAddress((void**)&h1lo,  g_h1lo);
    cudaGetSymbolAddress((void**)&w1thi, g_w1thi);
    cudaGetSymbolAddress((void**)&w1tlo, g_w1tlo);
    cudaGetSymbolAddress((void**)&w2thi, g_w2thi);
    cudaGetSymbolAddress((void**)&w2tlo, g_w2tlo);
    cudaGetSymbolAddress((void**)&h2,    g_h2);
    cudaGetSymbolAddress((void**)&topidx, g_topidx);
    cudaGetSymbolAddress((void**)&splen,  g_spanlen);

    cudaFuncSetAttribute(gemm3_mma<1>, cudaFuncAttributeMaxDynamicSharedMemorySize, GEMM_SMEM);
    cudaFuncSetAttribute(gemm3_mma<0>, cudaFuncAttributeMaxDynamicSharedMemorySize, GEMM_SMEM);
    cudaFuncSetAttribute(topk_kernel, cudaFuncAttributeMaxDynamicSharedMemorySize, 65536);

    // 1) split inputs + weights into hi/lo bf16 (WT is [N][K], K-major)
    {
        size_t n4 = (size_t)MM * DD / 4;
        split_kernel<<<(unsigned)((n4 + 255) / 256), 256>>>((const float4*)span_vecs, xhi, xlo, n4);
    }
    {
        size_t n = (size_t)DD * HH;
        transpose_split<<<(unsigned)((n + 255) / 256), 256>>>(W1, w1thi, w1tlo, DD, HH);
    }
    {
        size_t n = (size_t)HH * HH;
        transpose_split<<<(unsigned)((n + 255) / 256), 256>>>(W2, w2thi, w2tlo, HH, HH);
    }

    // 2) GEMM1: relu(x @ W1 + b1) -> h1 (split bf16 hi/lo)
    {
        dim3 grid(HH / GBN, MM / GBM);   // (8, 240)
        gemm3_mma<1><<<grid, 256, GEMM_SMEM>>>(xhi, xlo, w1thi, w1tlo, b1,
                                               nullptr, h1hi, h1lo, MM, HH, DD);
    }
    // 3) GEMM2: relu(h1 @ W2 + b2) -> h2 (fp32)
    {
        dim3 grid(HH / GBN, MM / GBM);
        gemm3_mma<0><<<grid, 256, GEMM_SMEM>>>(h1hi, h1lo, w2thi, w2tlo, b2,
                                               h2, nullptr, nullptr, MM, HH, HH);
    }

    // 4) scores + penalty
    score_kernel<<<MM / 8, 256>>>(h2, W3, b3, span_mask, out);

    // 5) top-K per batch
    topk_kernel<<<BB, 1024, 65536>>>(out, seqlen, out, topidx, splen);

    // 6) gathers
    gather_kernel<<<BB * KK, 256>>>(span_vecs, span_begin, span_end, topidx, out);

    // 7) masks
    {
        int n = BB * KK * KK;
        mask_kernel<<<(n + 255) / 256, 256>>>(splen, out);
    }
}

// round 5
// speedup vs baseline: 2.5885x; 1.1555x over previous
#include <cuda_runtime.h>
#include <cuda_bf16.h>
#include <cstdint>

// ---------------------------------------------------------------------------
// MentionPrunerSpanBert: B=4, T=512, L=15, D=2048, H=1024, K=205
// R4: (a) 2 CTAs/SM for the HMMA GEMMs (NSTAGE 3->2, reg diet to <=128 via
//         B-fragment register reuse across the 3 MMA terms)
//     (b) GEMM2 epilogue fuses the W3 GEMV -> deterministic per-block score
//         partials; h2 (125MB) is never materialized.
// ---------------------------------------------------------------------------

#define BB   4
#define TT   512
#define LL   15
#define DD   2048
#define HH   1024
#define KK   205
#define TL   (TT * LL)          // 7680
#define MM   (BB * TL)          // 30720
#define NPART 8                 // HH / GBN score partial blocks

#define O_PSCORE 0
#define O_TOPIDX (O_PSCORE + MM)
#define O_FVECS  (O_TOPIDX + BB * KK)
#define O_FSCORE (O_FVECS  + (size_t)BB * KK * DD)
#define O_FBEGIN (O_FSCORE + BB * KK)
#define O_FEND   (O_FBEGIN + BB * KK)
#define O_SPLEN  (O_FEND   + BB * KK)
#define O_SQMASK (O_SPLEN  + BB)
#define O_TRMASK (O_SQMASK + BB * KK * KK)

// ---------------- device scratch (no allocations allowed) -------------------
__device__ __nv_bfloat16 g_xhi[(size_t)MM * DD];
__device__ __nv_bfloat16 g_xlo[(size_t)MM * DD];
__device__ __nv_bfloat16 g_h1hi[(size_t)MM * HH];
__device__ __nv_bfloat16 g_h1lo[(size_t)MM * HH];
__device__ __nv_bfloat16 g_w1thi[(size_t)HH * DD];
__device__ __nv_bfloat16 g_w1tlo[(size_t)HH * DD];
__device__ __nv_bfloat16 g_w2thi[(size_t)HH * HH];
__device__ __nv_bfloat16 g_w2tlo[(size_t)HH * HH];
__device__ float g_spart[(size_t)MM * NPART];   // score partials [row][blockN]
__device__ int   g_topidx[BB * KK];
__device__ int   g_spanlen[BB];

// ---------------- PTX helpers (all arch-agnostic, sm_80+) -------------------
__device__ __forceinline__ uint32_t smem_u32_of(const void* p) {
    uint32_t a;
    asm("{ .reg .u64 t; cvta.to.shared.u64 t, %1; cvt.u32.u64 %0, t; }" : "=r"(a) : "l"(p));
    return a;
}
#define CP16(dst, src) \
    asm volatile("cp.async.cg.shared.global [%0], [%1], 16;" :: "r"((uint32_t)(dst)), "l"(src))
#define CP_COMMIT() asm volatile("cp.async.commit_group;" ::: "memory")
#define CP_WAIT(n)  asm volatile("cp.async.wait_group %0;" :: "n"(n) : "memory")

#define LDSM_X4(R0, R1, R2, R3, addr) \
    asm volatile("ldmatrix.sync.aligned.m8n8.x4.shared.b16 {%0,%1,%2,%3}, [%4];" \
        : "=r"(R0), "=r"(R1), "=r"(R2), "=r"(R3) : "r"(addr))

#define MMA_BF16(D, A, B0, B1) \
    asm volatile("mma.sync.aligned.m16n8k16.row.col.f32.bf16.bf16.f32 " \
        "{%0,%1,%2,%3}, {%4,%5,%6,%7}, {%8,%9}, {%0,%1,%2,%3};" \
        : "+f"((D)[0]), "+f"((D)[1]), "+f"((D)[2]), "+f"((D)[3]) \
        : "r"((A)[0]), "r"((A)[1]), "r"((A)[2]), "r"((A)[3]), "r"(B0), "r"(B1))

// ---------------------------------------------------------------------------
// Split / transpose-split preprocessing
// ---------------------------------------------------------------------------
__global__ void split_kernel(const float4* __restrict__ x,
                             __nv_bfloat16* __restrict__ hi,
                             __nv_bfloat16* __restrict__ lo, size_t n4)
{
    size_t i = (size_t)blockIdx.x * blockDim.x + threadIdx.x;
    if (i >= n4) return;
    float4 v = x[i];
    float vv[4] = {v.x, v.y, v.z, v.w};
    __nv_bfloat16 h[4], l[4];
#pragma unroll
    for (int k = 0; k < 4; k++) {
        h[k] = __float2bfloat16(vv[k]);
        l[k] = __float2bfloat16(vv[k] - __bfloat162float(h[k]));
    }
    __nv_bfloat162 h01, h23, l01, l23;
    h01.x = h[0]; h01.y = h[1]; h23.x = h[2]; h23.y = h[3];
    l01.x = l[0]; l01.y = l[1]; l23.x = l[2]; l23.y = l[3];
    __nv_bfloat162* hp = reinterpret_cast<__nv_bfloat162*>(hi) + 2 * i;
    __nv_bfloat162* lp = reinterpret_cast<__nv_bfloat162*>(lo) + 2 * i;
    hp[0] = h01; hp[1] = h23;
    lp[0] = l01; lp[1] = l23;
}

// W [K,N] row-major -> WT [N,K] (K-major) split into hi/lo bf16
__global__ void transpose_split(const float* __restrict__ W,
                                __nv_bfloat16* __restrict__ Thi,
                                __nv_bfloat16* __restrict__ Tlo, int Kd, int N)
{
    size_t tid = (size_t)blockIdx.x * blockDim.x + threadIdx.x;
    if (tid >= (size_t)Kd * N) return;
    int k = (int)(tid % Kd);
    int n = (int)(tid / Kd);
    float v = W[(size_t)k * N + n];
    __nv_bfloat16 h = __float2bfloat16(v);
    Thi[tid] = h;
    Tlo[tid] = __float2bfloat16(v - __bfloat162float(h));
}

// ---------------------------------------------------------------------------
// Split-bf16 HMMA GEMM:  C[M,N] = relu((Ahi+Alo) @ (Bhi+Blo)^T + bias)
//   Tile 128x128, BK=32, 256 threads (4m x 2n warps, warp tile 32x64),
//   2-stage cp.async pipeline (2 CTAs/SM), 3 MMA terms, B-frag reg reuse.
//   MODE 1: write Chi/Clo bf16 (re-split h1).
//   MODE 2: fused W3 GEMV -> deterministic partials spart[row*NPART+blockN].
// ---------------------------------------------------------------------------
#define GBM 128
#define GBN 128
#define GBK 32
#define ROWB 80
#define SM_AH 0
#define SM_AL (128 * ROWB)
#define SM_BH (2 * 128 * ROWB)
#define SM_BL (3 * 128 * ROWB)
#define STAGE_SZ (4 * 128 * ROWB)     // 40960
#define NSTAGE 2
#define GEMM_SMEM (NSTAGE * STAGE_SZ) // 81920

template <int MODE>
__global__ __launch_bounds__(256, 2)
void gemm3_mma(const __nv_bfloat16* __restrict__ Ahi, const __nv_bfloat16* __restrict__ Alo,
               const __nv_bfloat16* __restrict__ Bhi, const __nv_bfloat16* __restrict__ Blo,
               const float* __restrict__ bias,
               const float* __restrict__ W3,
               float* __restrict__ spart,
               __nv_bfloat16* __restrict__ Chi, __nv_bfloat16* __restrict__ Clo,
               int M, int N, int Kd)
{
    extern __shared__ char smem[];
    const uint32_t sb = smem_u32_of(smem);
    const int t = threadIdx.x;
    const int lane = t & 31;
    const int wid = t >> 5;
    const int wm = wid & 3;
    const int wn = wid >> 2;
    const int mBase = blockIdx.y * GBM;
    const int nBase = blockIdx.x * GBN;
    const int NC = Kd / GBK;

    float acc[2][8][4];
#pragma unroll
    for (int mi = 0; mi < 2; mi++)
#pragma unroll
        for (int ni = 0; ni < 8; ni++)
#pragma unroll
            for (int j = 0; j < 4; j++) acc[mi][ni][j] = 0.0f;

    auto load_stage = [&](int cidx, int buf) {
        const size_t ko = (size_t)cidx * GBK;
        const uint32_t stg = sb + buf * STAGE_SZ;
#pragma unroll
        for (int p = 0; p < 2; p++) {
            const int idx = t + p * 256;
            const int row = idx >> 2;
            const int c16 = idx & 3;
            const uint32_t doff = row * ROWB + c16 * 16;
            const size_t aoff = (size_t)(mBase + row) * Kd + ko + c16 * 8;
            const size_t boff = (size_t)(nBase + row) * Kd + ko + c16 * 8;
            CP16(stg + SM_AH + doff, Ahi + aoff);
            CP16(stg + SM_AL + doff, Alo + aoff);
            CP16(stg + SM_BH + doff, Bhi + boff);
            CP16(stg + SM_BL + doff, Blo + boff);
        }
        CP_COMMIT();
    };

    load_stage(0, 0);
    load_stage(1, 1);

    const int ar = lane & 15, ac = lane >> 4;
    const int br = lane & 7,  bblk = lane >> 3;

#pragma unroll 1
    for (int c = 0; c < NC; c++) {
        const int buf = c & 1;
        if (c < NC - 1) CP_WAIT(1); else CP_WAIT(0);
        __syncthreads();

        const uint32_t stg = sb + buf * STAGE_SZ;
#pragma unroll
        for (int kk2 = 0; kk2 < 2; kk2++) {
            const int kb = kk2 * 32;
            uint32_t ah[2][4], al[2][4];
#pragma unroll
            for (int mi = 0; mi < 2; mi++) {
                const uint32_t ra = (wm * 32 + mi * 16 + ar) * ROWB + kb + ac * 16;
                LDSM_X4(ah[mi][0], ah[mi][1], ah[mi][2], ah[mi][3], stg + SM_AH + ra);
                LDSM_X4(al[mi][0], al[mi][1], al[mi][2], al[mi][3], stg + SM_AL + ra);
            }
            uint32_t bf[8][2];
            // --- B hi: terms Ahi*Bhi + Alo*Bhi ---
#pragma unroll
            for (int nj = 0; nj < 4; nj++) {
                const uint32_t rb = (wn * 64 + nj * 16 + (bblk >> 1) * 8 + br) * ROWB
                                    + kb + (bblk & 1) * 16;
                LDSM_X4(bf[2*nj][0], bf[2*nj][1], bf[2*nj+1][0], bf[2*nj+1][1], stg + SM_BH + rb);
            }
#pragma unroll
            for (int mi = 0; mi < 2; mi++)
#pragma unroll
                for (int ni = 0; ni < 8; ni++) {
                    MMA_BF16(acc[mi][ni], ah[mi], bf[ni][0], bf[ni][1]);
                    MMA_BF16(acc[mi][ni], al[mi], bf[ni][0], bf[ni][1]);
                }
            // --- B lo: term Ahi*Blo (reuse bf regs) ---
#pragma unroll
            for (int nj = 0; nj < 4; nj++) {
                const uint32_t rb = (wn * 64 + nj * 16 + (bblk >> 1) * 8 + br) * ROWB
                                    + kb + (bblk & 1) * 16;
                LDSM_X4(bf[2*nj][0], bf[2*nj][1], bf[2*nj+1][0], bf[2*nj+1][1], stg + SM_BL + rb);
            }
#pragma unroll
            for (int mi = 0; mi < 2; mi++)
#pragma unroll
                for (int ni = 0; ni < 8; ni++)
                    MMA_BF16(acc[mi][ni], ah[mi], bf[ni][0], bf[ni][1]);
        }

        if (c + 2 < NC) {
            __syncthreads();            // all reads of buf done before overwrite
            load_stage(c + 2, buf);
        }
    }

    // ---- epilogue ----
    const int r0 = lane >> 2;
    const int c0 = (lane & 3) << 1;

    if (MODE == 1) {
#pragma unroll
        for (int mi = 0; mi < 2; mi++) {
            const int rowA = mBase + wm * 32 + mi * 16 + r0;
#pragma unroll
            for (int ni = 0; ni < 8; ni++) {
                const int col = nBase + wn * 64 + ni * 8 + c0;
                const float bv0 = bias[col], bv1 = bias[col + 1];
                float v0 = acc[mi][ni][0] + bv0;  v0 = v0 > 0.0f ? v0 : 0.0f;
                float v1 = acc[mi][ni][1] + bv1;  v1 = v1 > 0.0f ? v1 : 0.0f;
                float v2 = acc[mi][ni][2] + bv0;  v2 = v2 > 0.0f ? v2 : 0.0f;
                float v3 = acc[mi][ni][3] + bv1;  v3 = v3 > 0.0f ? v3 : 0.0f;
                __nv_bfloat16 h0 = __float2bfloat16(v0), h1 = __float2bfloat16(v1);
                __nv_bfloat16 h2 = __float2bfloat16(v2), h3 = __float2bfloat16(v3);
                __nv_bfloat162 hh, ll;
                hh.x = h0; hh.y = h1;
                ll.x = __float2bfloat16(v0 - __bfloat162float(h0));
                ll.y = __float2bfloat16(v1 - __bfloat162float(h1));
                *reinterpret_cast<__nv_bfloat162*>(Chi + (size_t)rowA * N + col) = hh;
                *reinterpret_cast<__nv_bfloat162*>(Clo + (size_t)rowA * N + col) = ll;
                hh.x = h2; hh.y = h3;
                ll.x = __float2bfloat16(v2 - __bfloat162float(h2));
                ll.y = __float2bfloat16(v3 - __bfloat162float(h3));
                *reinterpret_cast<__nv_bfloat162*>(Chi + (size_t)(rowA + 8) * N + col) = hh;
                *reinterpret_cast<__nv_bfloat162*>(Clo + (size_t)(rowA + 8) * N + col) = ll;
            }
        }
    } else {
        // fused W3 GEMV: ps[mi][h] = partial dot over this thread's 16 cols
        float ps[2][2] = {{0.0f, 0.0f}, {0.0f, 0.0f}};
#pragma unroll
        for (int mi = 0; mi < 2; mi++) {
#pragma unroll
            for (int ni = 0; ni < 8; ni++) {
                const int col = nBase + wn * 64 + ni * 8 + c0;
                const float bv0 = bias[col], bv1 = bias[col + 1];
                const float w0 = W3[col], w1 = W3[col + 1];
                float v0 = acc[mi][ni][0] + bv0;  v0 = v0 > 0.0f ? v0 : 0.0f;
                float v1 = acc[mi][ni][1] + bv1;  v1 = v1 > 0.0f ? v1 : 0.0f;
                float v2 = acc[mi][ni][2] + bv0;  v2 = v2 > 0.0f ? v2 : 0.0f;
                float v3 = acc[mi][ni][3] + bv1;  v3 = v3 > 0.0f ? v3 : 0.0f;
                ps[mi][0] = fmaf(v0, w0, fmaf(v1, w1, ps[mi][0]));
                ps[mi][1] = fmaf(v2, w0, fmaf(v3, w1, ps[mi][1]));
            }
            // reduce across the 4-lane column group (lanes differing in bits 0,1)
#pragma unroll
            for (int o = 1; o <= 2; o <<= 1) {
                ps[mi][0] += __shfl_xor_sync(0xffffffffu, ps[mi][0], o);
                ps[mi][1] += __shfl_xor_sync(0xffffffffu, ps[mi][1], o);
            }
        }
        // combine across wn via smem (pipeline smem reusable after sync)
        float* pssum = reinterpret_cast<float*>(smem);   // [128][2]
        __syncthreads();
        if ((lane & 3) == 0) {
#pragma unroll
            for (int mi = 0; mi < 2; mi++) {
                int lr = wm * 32 + mi * 16 + r0;
                pssum[(lr)     * 2 + wn] = ps[mi][0];
                pssum[(lr + 8) * 2 + wn] = ps[mi][1];
            }
        }
        __syncthreads();
        if (t < 128) {
            float s = pssum[t * 2] + pssum[t * 2 + 1];
            spart[(size_t)(mBase + t) * NPART + blockIdx.x] = s;
        }
    }
}

// ---------------------------------------------------------------------------
// Final score: sum NPART partials + b3 + mask penalty -> prune_scores
// ---------------------------------------------------------------------------
__global__ void score_finish(const float* __restrict__ spart,
                             const float* __restrict__ b3,
                             const float* __restrict__ mask,
                             float* __restrict__ out)
{
    int row = blockIdx.x * blockDim.x + threadIdx.x;
    if (row >= MM) return;
    const float* p = spart + (size_t)row * NPART;
    float s = b3[0];
#pragma unroll
    for (int j = 0; j < NPART; j++) s += p[j];
    out[O_PSCORE + row] = s - (1.0f - mask[row]) * 10000.0f;
}

// ---------------------------------------------------------------------------
// Per-batch top-K (bitonic, proven)
// ---------------------------------------------------------------------------
__global__ void topk_kernel(const float* __restrict__ out_ro,
                            const int* __restrict__ seqlen,
                            float* __restrict__ out,
                            int* __restrict__ topidx,
                            int* __restrict__ splen)
{
    extern __shared__ unsigned long long key[];
    const int b = blockIdx.x;
    const int t = threadIdx.x;

    for (int i = t; i < 8192; i += 1024) {
        unsigned long long kv;
        if (i < TL) {
            float s = out_ro[O_PSCORE + b * TL + i];
            unsigned u = __float_as_uint(s);
            u = (u & 0x80000000u) ? ~u : (u | 0x80000000u);
            kv = ((unsigned long long)(~u) << 32) | (unsigned)i;
        } else kv = 0xFFFFFFFFFFFFFFFFull;
        key[i] = kv;
    }
    __syncthreads();

    for (int k = 2; k <= 8192; k <<= 1)
        for (int j = k >> 1; j > 0; j >>= 1) {
            for (int i = t; i < 8192; i += 1024) {
                int ixj = i ^ j;
                if (ixj > i) {
                    unsigned long long a = key[i], c = key[ixj];
                    bool up = ((i & k) == 0);
                    if ((a > c) == up) { key[i] = c; key[ixj] = a; }
                }
            }
            __syncthreads();
        }

    __shared__ int sidx[256];
    if (t < 256) sidx[t] = (t < KK) ? (int)(key[t] & 0xFFFFFFFFull) : 0x7FFFFFFF;
    __syncthreads();
    for (int k = 2; k <= 256; k <<= 1)
        for (int j = k >> 1; j > 0; j >>= 1) {
            if (t < 256) {
                int i = t, ixj = i ^ j;
                if (ixj > i) {
                    int a = sidx[i], c = sidx[ixj];
                    bool up = ((i & k) == 0);
                    if ((a > c) == up) { sidx[i] = c; sidx[ixj] = a; }
                }
            }
            __syncthreads();
        }

    if (t < KK) {
        topidx[b * KK + t] = sidx[t];
        out[O_TOPIDX + b * KK + t] = (float)sidx[t];
    }
    if (t == 0) {
        int len = (int)ceilf((float)seqlen[b] * 0.4f);
        splen[b] = len;
        out[O_SPLEN + b] = (float)len;
    }
}

__global__ void gather_kernel(const float* __restrict__ span_vecs,
                              const int* __restrict__ span_begin,
                              const int* __restrict__ span_end,
                              const int* __restrict__ topidx,
                              float* __restrict__ out)
{
    int blk = blockIdx.x;
    int b = blk / KK, k = blk % KK;
    int idx = topidx[b * KK + k];
    const float* src = span_vecs + ((size_t)b * TL + idx) * DD;
    float* dst = out + O_FVECS + ((size_t)b * KK + k) * DD;
    for (int i = threadIdx.x; i < DD; i += 256) dst[i] = src[i];
    if (threadIdx.x == 0) {
        int g = b * TL + idx;
        out[O_FSCORE + b * KK + k] = out[O_PSCORE + g];
        out[O_FBEGIN + b * KK + k] = (float)span_begin[g];
        out[O_FEND   + b * KK + k] = (float)span_end[g];
    }
}

__global__ void mask_kernel(const int* __restrict__ splen, float* __restrict__ out)
{
    int i = blockIdx.x * blockDim.x + threadIdx.x;
    const int per = KK * KK;
    if (i >= BB * per) return;
    int b = i / per, r = i % per;
    int ii = r / KK, jj = r % KK;
    int len = splen[b];
    float v = (ii < len && jj < len) ? 1.0f : 0.0f;
    out[O_SQMASK + i] = v;
    out[O_TRMASK + i] = (jj <= ii) ? v : 0.0f;
}

// ---------------------------------------------------------------------------
extern "C" void kernel_launch(void* const* d_in, const int* in_sizes, int n_in,
                              void* d_out, int out_size)
{
    const float* span_vecs  = (const float*)d_in[0];
    const float* span_mask  = (const float*)d_in[1];
    const int*   span_begin = (const int*)  d_in[2];
    const int*   span_end   = (const int*)  d_in[3];
    const int*   seqlen     = (const int*)  d_in[4];
    const float* W1 = (const float*)d_in[5];
    const float* b1 = (const float*)d_in[6];
    const float* W2 = (const float*)d_in[7];
    const float* b2 = (const float*)d_in[8];
    const float* W3 = (const float*)d_in[9];
    const float* b3 = (const float*)d_in[10];
    float* out = (float*)d_out;

    __nv_bfloat16 *xhi, *xlo, *h1hi, *h1lo, *w1thi, *w1tlo, *w2thi, *w2tlo;
    float* spart; int *topidx, *splen;
    cudaGetSymbolAddress((void**)&xhi,   g_xhi);
    cudaGetSymbolAddress((void**)&xlo,   g_xlo);
    cudaGetSymbolAddress((void**)&h1hi,  g_h1hi);
    cudaGetSymbolAddress((void**)&h1lo,  g_h1lo);
    cudaGetSymbolAddress((void**)&w1thi, g_w1thi);
    cudaGetSymbolAddress((void**)&w1tlo, g_w1tlo);
    cudaGetSymbolAddress((void**)&w2thi, g_w2thi);
    cudaGetSymbolAddress((void**)&w2tlo, g_w2tlo);
    cudaGetSymbolAddress((void**)&spart, g_spart);
    cudaGetSymbolAddress((void**)&topidx, g_topidx);
    cudaGetSymbolAddress((void**)&splen,  g_spanlen);

    cudaFuncSetAttribute(gemm3_mma<1>, cudaFuncAttributeMaxDynamicSharedMemorySize, GEMM_SMEM);
    cudaFuncSetAttribute(gemm3_mma<2>, cudaFuncAttributeMaxDynamicSharedMemorySize, GEMM_SMEM);
    cudaFuncSetAttribute(topk_kernel, cudaFuncAttributeMaxDynamicSharedMemorySize, 65536);

    // 1) split inputs + weights into hi/lo bf16 (WT is [N][K], K-major)
    {
        size_t n4 = (size_t)MM * DD / 4;
        split_kernel<<<(unsigned)((n4 + 255) / 256), 256>>>((const float4*)span_vecs, xhi, xlo, n4);
    }
    {
        size_t n = (size_t)DD * HH;
        transpose_split<<<(unsigned)((n + 255) / 256), 256>>>(W1, w1thi, w1tlo, DD, HH);
    }
    {
        size_t n = (size_t)HH * HH;
        transpose_split<<<(unsigned)((n + 255) / 256), 256>>>(W2, w2thi, w2tlo, HH, HH);
    }

    // 2) GEMM1: relu(x @ W1 + b1) -> h1 (split bf16 hi/lo)
    {
        dim3 grid(HH / GBN, MM / GBM);   // (8, 240)
        gemm3_mma<1><<<grid, 256, GEMM_SMEM>>>(xhi, xlo, w1thi, w1tlo, b1,
                                               nullptr, nullptr, h1hi, h1lo, MM, HH, DD);
    }
    // 3) GEMM2 + fused W3 GEMV -> score partials (h2 never materialized)
    {
        dim3 grid(HH / GBN, MM / GBM);
        gemm3_mma<2><<<grid, 256, GEMM_SMEM>>>(h1hi, h1lo, w2thi, w2tlo, b2,
                                               W3, spart, nullptr, nullptr, MM, HH, HH);
    }

    // 4) finish scores + penalty
    score_finish<<<(MM + 255) / 256, 256>>>(spart, b3, span_mask, out);

    // 5) top-K per batch
    topk_kernel<<<BB, 1024, 65536>>>(out, seqlen, out, topidx, splen);

    // 6) gathers
    gather_kernel<<<BB * KK, 256>>>(span_vecs, span_begin, span_end, topidx, out);

    // 7) masks
    {
        int n = BB * KK * KK;
        mask_kernel<<<(n + 255) / 256, 256>>>(splen, out);
    }
}

// round 6
// speedup vs baseline: 3.1017x; 1.1982x over previous
#include <cuda_runtime.h>
#include <cuda_bf16.h>
#include <cstdint>

// ---------------------------------------------------------------------------
// MentionPrunerSpanBert: B=4, T=512, L=15, D=2048, H=1024, K=205
// R5: swizzled smem (ROWB 80 -> 64, XOR-swizzle on 16B chunks) shrinks the
//     pipeline stage to 32KB -> NSTAGE=3 with 2 CTAs/SM AND a single
//     __syncthreads per K-chunk (R3 schedule at R4 occupancy).
// ---------------------------------------------------------------------------

#define BB   4
#define TT   512
#define LL   15
#define DD   2048
#define HH   1024
#define KK   205
#define TL   (TT * LL)          // 7680
#define MM   (BB * TL)          // 30720
#define NPART 8                 // HH / GBN score partial blocks

#define O_PSCORE 0
#define O_TOPIDX (O_PSCORE + MM)
#define O_FVECS  (O_TOPIDX + BB * KK)
#define O_FSCORE (O_FVECS  + (size_t)BB * KK * DD)
#define O_FBEGIN (O_FSCORE + BB * KK)
#define O_FEND   (O_FBEGIN + BB * KK)
#define O_SPLEN  (O_FEND   + BB * KK)
#define O_SQMASK (O_SPLEN  + BB)
#define O_TRMASK (O_SQMASK + BB * KK * KK)

// ---------------- device scratch (no allocations allowed) -------------------
__device__ __nv_bfloat16 g_xhi[(size_t)MM * DD];
__device__ __nv_bfloat16 g_xlo[(size_t)MM * DD];
__device__ __nv_bfloat16 g_h1hi[(size_t)MM * HH];
__device__ __nv_bfloat16 g_h1lo[(size_t)MM * HH];
__device__ __nv_bfloat16 g_w1thi[(size_t)HH * DD];
__device__ __nv_bfloat16 g_w1tlo[(size_t)HH * DD];
__device__ __nv_bfloat16 g_w2thi[(size_t)HH * HH];
__device__ __nv_bfloat16 g_w2tlo[(size_t)HH * HH];
__device__ float g_spart[(size_t)MM * NPART];
__device__ int   g_topidx[BB * KK];
__device__ int   g_spanlen[BB];

// ---------------- PTX helpers (all arch-agnostic, sm_80+) -------------------
__device__ __forceinline__ uint32_t smem_u32_of(const void* p) {
    uint32_t a;
    asm("{ .reg .u64 t; cvta.to.shared.u64 t, %1; cvt.u32.u64 %0, t; }" : "=r"(a) : "l"(p));
    return a;
}
#define CP16(dst, src) \
    asm volatile("cp.async.cg.shared.global [%0], [%1], 16;" :: "r"((uint32_t)(dst)), "l"(src))
#define CP_COMMIT() asm volatile("cp.async.commit_group;" ::: "memory")
#define CP_WAIT(n)  asm volatile("cp.async.wait_group %0;" :: "n"(n) : "memory")

#define LDSM_X4(R0, R1, R2, R3, addr) \
    asm volatile("ldmatrix.sync.aligned.m8n8.x4.shared.b16 {%0,%1,%2,%3}, [%4];" \
        : "=r"(R0), "=r"(R1), "=r"(R2), "=r"(R3) : "r"(addr))

#define MMA_BF16(D, A, B0, B1) \
    asm volatile("mma.sync.aligned.m16n8k16.row.col.f32.bf16.bf16.f32 " \
        "{%0,%1,%2,%3}, {%4,%5,%6,%7}, {%8,%9}, {%0,%1,%2,%3};" \
        : "+f"((D)[0]), "+f"((D)[1]), "+f"((D)[2]), "+f"((D)[3]) \
        : "r"((A)[0]), "r"((A)[1]), "r"((A)[2]), "r"((A)[3]), "r"(B0), "r"(B1))

// Swizzled smem offset for (row, 16B-chunk c in 0..3), 64B row pitch.
// Bank(row,p) = (16*row + 4p) mod 32: same-parity rows alias; (row>>1)&3 is a
// bijection within each parity class of 8 rows -> ldmatrix phases conflict-free.
__device__ __forceinline__ uint32_t swz(int row, int chunk) {
    return (uint32_t)(row * 64 + (((chunk) ^ ((row >> 1) & 3)) & 3) * 16);
}

// ---------------------------------------------------------------------------
// Split / transpose-split preprocessing
// ---------------------------------------------------------------------------
__global__ void split_kernel(const float4* __restrict__ x,
                             __nv_bfloat16* __restrict__ hi,
                             __nv_bfloat16* __restrict__ lo, size_t n4)
{
    size_t i = (size_t)blockIdx.x * blockDim.x + threadIdx.x;
    if (i >= n4) return;
    float4 v = x[i];
    float vv[4] = {v.x, v.y, v.z, v.w};
    __nv_bfloat16 h[4], l[4];
#pragma unroll
    for (int k = 0; k < 4; k++) {
        h[k] = __float2bfloat16(vv[k]);
        l[k] = __float2bfloat16(vv[k] - __bfloat162float(h[k]));
    }
    __nv_bfloat162 h01, h23, l01, l23;
    h01.x = h[0]; h01.y = h[1]; h23.x = h[2]; h23.y = h[3];
    l01.x = l[0]; l01.y = l[1]; l23.x = l[2]; l23.y = l[3];
    __nv_bfloat162* hp = reinterpret_cast<__nv_bfloat162*>(hi) + 2 * i;
    __nv_bfloat162* lp = reinterpret_cast<__nv_bfloat162*>(lo) + 2 * i;
    hp[0] = h01; hp[1] = h23;
    lp[0] = l01; lp[1] = l23;
}

__global__ void transpose_split(const float* __restrict__ W,
                                __nv_bfloat16* __restrict__ Thi,
                                __nv_bfloat16* __restrict__ Tlo, int Kd, int N)
{
    size_t tid = (size_t)blockIdx.x * blockDim.x + threadIdx.x;
    if (tid >= (size_t)Kd * N) return;
    int k = (int)(tid % Kd);
    int n = (int)(tid / Kd);
    float v = W[(size_t)k * N + n];
    __nv_bfloat16 h = __float2bfloat16(v);
    Thi[tid] = h;
    Tlo[tid] = __float2bfloat16(v - __bfloat162float(h));
}

// ---------------------------------------------------------------------------
// Split-bf16 HMMA GEMM, tile 128x128, BK=32, 256 thr (4m x 2n warps),
// 3-stage cp.async pipeline, swizzled smem, ONE sync per chunk, 2 CTAs/SM.
//   MODE 1: write Chi/Clo bf16 (re-split h1).
//   MODE 2: fused W3 GEMV -> deterministic partials spart[row*NPART+blockN].
// ---------------------------------------------------------------------------
#define GBM 128
#define GBN 128
#define GBK 32
#define SM_AH 0
#define SM_AL 8192
#define SM_BH 16384
#define SM_BL 24576
#define STAGE_SZ 32768
#define NSTAGE 3
#define GEMM_SMEM (NSTAGE * STAGE_SZ)   // 98304 -> 2 CTAs/SM (196.6KB)

template <int MODE>
__global__ __launch_bounds__(256, 2)
void gemm3_mma(const __nv_bfloat16* __restrict__ Ahi, const __nv_bfloat16* __restrict__ Alo,
               const __nv_bfloat16* __restrict__ Bhi, const __nv_bfloat16* __restrict__ Blo,
               const float* __restrict__ bias,
               const float* __restrict__ W3,
               float* __restrict__ spart,
               __nv_bfloat16* __restrict__ Chi, __nv_bfloat16* __restrict__ Clo,
               int M, int N, int Kd)
{
    extern __shared__ char smem[];
    const uint32_t sb = smem_u32_of(smem);
    const int t = threadIdx.x;
    const int lane = t & 31;
    const int wid = t >> 5;
    const int wm = wid & 3;
    const int wn = wid >> 2;
    const int mBase = blockIdx.y * GBM;
    const int nBase = blockIdx.x * GBN;
    const int NC = Kd / GBK;

    float acc[2][8][4];
#pragma unroll
    for (int mi = 0; mi < 2; mi++)
#pragma unroll
        for (int ni = 0; ni < 8; ni++)
#pragma unroll
            for (int j = 0; j < 4; j++) acc[mi][ni][j] = 0.0f;

    auto load_stage = [&](int cidx, int buf) {
        const size_t ko = (size_t)cidx * GBK;
        const uint32_t stg = sb + buf * STAGE_SZ;
#pragma unroll
        for (int p = 0; p < 2; p++) {
            const int idx = t + p * 256;
            const int row = idx >> 2;
            const int c16 = idx & 3;
            const uint32_t doff = swz(row, c16);
            const size_t aoff = (size_t)(mBase + row) * Kd + ko + c16 * 8;
            const size_t boff = (size_t)(nBase + row) * Kd + ko + c16 * 8;
            CP16(stg + SM_AH + doff, Ahi + aoff);
            CP16(stg + SM_AL + doff, Alo + aoff);
            CP16(stg + SM_BH + doff, Bhi + boff);
            CP16(stg + SM_BL + doff, Blo + boff);
        }
        CP_COMMIT();
    };

    load_stage(0, 0);
    load_stage(1, 1);

    const int ar = lane & 15, ac = lane >> 4;
    const int br = lane & 7,  bblk = lane >> 3;

#pragma unroll 1
    for (int c = 0; c < NC; c++) {
        const int buf = c % NSTAGE;
        if (c < NC - 1) CP_WAIT(1); else CP_WAIT(0);
        __syncthreads();
        // prefetch into buffer (c-1)%NSTAGE: drained by the sync above
        if (c + 2 < NC) load_stage(c + 2, (c + 2) % NSTAGE);

        const uint32_t stg = sb + buf * STAGE_SZ;
#pragma unroll
        for (int kk2 = 0; kk2 < 2; kk2++) {
            uint32_t ah[2][4], al[2][4];
#pragma unroll
            for (int mi = 0; mi < 2; mi++) {
                const int rowA = wm * 32 + mi * 16 + ar;
                const uint32_t ra = swz(rowA, kk2 * 2 + ac);
                LDSM_X4(ah[mi][0], ah[mi][1], ah[mi][2], ah[mi][3], stg + SM_AH + ra);
                LDSM_X4(al[mi][0], al[mi][1], al[mi][2], al[mi][3], stg + SM_AL + ra);
            }
            uint32_t bf[8][2];
            // --- B hi: terms Ahi*Bhi + Alo*Bhi ---
#pragma unroll
            for (int nj = 0; nj < 4; nj++) {
                const int rowB = wn * 64 + nj * 16 + (bblk >> 1) * 8 + br;
                const uint32_t rb = swz(rowB, kk2 * 2 + (bblk & 1));
                LDSM_X4(bf[2*nj][0], bf[2*nj][1], bf[2*nj+1][0], bf[2*nj+1][1], stg + SM_BH + rb);
            }
#pragma unroll
            for (int mi = 0; mi < 2; mi++)
#pragma unroll
                for (int ni = 0; ni < 8; ni++) {
                    MMA_BF16(acc[mi][ni], ah[mi], bf[ni][0], bf[ni][1]);
                    MMA_BF16(acc[mi][ni], al[mi], bf[ni][0], bf[ni][1]);
                }
            // --- B lo: term Ahi*Blo (reuse bf regs) ---
#pragma unroll
            for (int nj = 0; nj < 4; nj++) {
                const int rowB = wn * 64 + nj * 16 + (bblk >> 1) * 8 + br;
                const uint32_t rb = swz(rowB, kk2 * 2 + (bblk & 1));
                LDSM_X4(bf[2*nj][0], bf[2*nj][1], bf[2*nj+1][0], bf[2*nj+1][1], stg + SM_BL + rb);
            }
#pragma unroll
            for (int mi = 0; mi < 2; mi++)
#pragma unroll
                for (int ni = 0; ni < 8; ni++)
                    MMA_BF16(acc[mi][ni], ah[mi], bf[ni][0], bf[ni][1]);
        }
    }

    // ---- epilogue ----
    const int r0 = lane >> 2;
    const int c0 = (lane & 3) << 1;

    if (MODE == 1) {
#pragma unroll
        for (int mi = 0; mi < 2; mi++) {
            const int rowA = mBase + wm * 32 + mi * 16 + r0;
#pragma unroll
            for (int ni = 0; ni < 8; ni++) {
                const int col = nBase + wn * 64 + ni * 8 + c0;
                const float bv0 = bias[col], bv1 = bias[col + 1];
                float v0 = acc[mi][ni][0] + bv0;  v0 = v0 > 0.0f ? v0 : 0.0f;
                float v1 = acc[mi][ni][1] + bv1;  v1 = v1 > 0.0f ? v1 : 0.0f;
                float v2 = acc[mi][ni][2] + bv0;  v2 = v2 > 0.0f ? v2 : 0.0f;
                float v3 = acc[mi][ni][3] + bv1;  v3 = v3 > 0.0f ? v3 : 0.0f;
                __nv_bfloat16 h0 = __float2bfloat16(v0), h1 = __float2bfloat16(v1);
                __nv_bfloat16 h2 = __float2bfloat16(v2), h3 = __float2bfloat16(v3);
                __nv_bfloat162 hh, ll;
                hh.x = h0; hh.y = h1;
                ll.x = __float2bfloat16(v0 - __bfloat162float(h0));
                ll.y = __float2bfloat16(v1 - __bfloat162float(h1));
                *reinterpret_cast<__nv_bfloat162*>(Chi + (size_t)rowA * N + col) = hh;
                *reinterpret_cast<__nv_bfloat162*>(Clo + (size_t)rowA * N + col) = ll;
                hh.x = h2; hh.y = h3;
                ll.x = __float2bfloat16(v2 - __bfloat162float(h2));
                ll.y = __float2bfloat16(v3 - __bfloat162float(h3));
                *reinterpret_cast<__nv_bfloat162*>(Chi + (size_t)(rowA + 8) * N + col) = hh;
                *reinterpret_cast<__nv_bfloat162*>(Clo + (size_t)(rowA + 8) * N + col) = ll;
            }
        }
    } else {
        float ps[2][2] = {{0.0f, 0.0f}, {0.0f, 0.0f}};
#pragma unroll
        for (int mi = 0; mi < 2; mi++) {
#pragma unroll
            for (int ni = 0; ni < 8; ni++) {
                const int col = nBase + wn * 64 + ni * 8 + c0;
                const float bv0 = bias[col], bv1 = bias[col + 1];
                const float w0 = W3[col], w1 = W3[col + 1];
                float v0 = acc[mi][ni][0] + bv0;  v0 = v0 > 0.0f ? v0 : 0.0f;
                float v1 = acc[mi][ni][1] + bv1;  v1 = v1 > 0.0f ? v1 : 0.0f;
                float v2 = acc[mi][ni][2] + bv0;  v2 = v2 > 0.0f ? v2 : 0.0f;
                float v3 = acc[mi][ni][3] + bv1;  v3 = v3 > 0.0f ? v3 : 0.0f;
                ps[mi][0] = fmaf(v0, w0, fmaf(v1, w1, ps[mi][0]));
                ps[mi][1] = fmaf(v2, w0, fmaf(v3, w1, ps[mi][1]));
            }
#pragma unroll
            for (int o = 1; o <= 2; o <<= 1) {
                ps[mi][0] += __shfl_xor_sync(0xffffffffu, ps[mi][0], o);
                ps[mi][1] += __shfl_xor_sync(0xffffffffu, ps[mi][1], o);
            }
        }
        float* pssum = reinterpret_cast<float*>(smem);   // [128][2]
        __syncthreads();
        if ((lane & 3) == 0) {
#pragma unroll
            for (int mi = 0; mi < 2; mi++) {
                int lr = wm * 32 + mi * 16 + r0;
                pssum[(lr)     * 2 + wn] = ps[mi][0];
                pssum[(lr + 8) * 2 + wn] = ps[mi][1];
            }
        }
        __syncthreads();
        if (t < 128) {
            float s = pssum[t * 2] + pssum[t * 2 + 1];
            spart[(size_t)(mBase + t) * NPART + blockIdx.x] = s;
        }
    }
}

// ---------------------------------------------------------------------------
__global__ void score_finish(const float* __restrict__ spart,
                             const float* __restrict__ b3,
                             const float* __restrict__ mask,
                             float* __restrict__ out)
{
    int row = blockIdx.x * blockDim.x + threadIdx.x;
    if (row >= MM) return;
    const float* p = spart + (size_t)row * NPART;
    float s = b3[0];
#pragma unroll
    for (int j = 0; j < NPART; j++) s += p[j];
    out[O_PSCORE + row] = s - (1.0f - mask[row]) * 10000.0f;
}

// ---------------------------------------------------------------------------
__global__ void topk_kernel(const float* __restrict__ out_ro,
                            const int* __restrict__ seqlen,
                            float* __restrict__ out,
                            int* __restrict__ topidx,
                            int* __restrict__ splen)
{
    extern __shared__ unsigned long long key[];
    const int b = blockIdx.x;
    const int t = threadIdx.x;

    for (int i = t; i < 8192; i += 1024) {
        unsigned long long kv;
        if (i < TL) {
            float s = out_ro[O_PSCORE + b * TL + i];
            unsigned u = __float_as_uint(s);
            u = (u & 0x80000000u) ? ~u : (u | 0x80000000u);
            kv = ((unsigned long long)(~u) << 32) | (unsigned)i;
        } else kv = 0xFFFFFFFFFFFFFFFFull;
        key[i] = kv;
    }
    __syncthreads();

    for (int k = 2; k <= 8192; k <<= 1)
        for (int j = k >> 1; j > 0; j >>= 1) {
            for (int i = t; i < 8192; i += 1024) {
                int ixj = i ^ j;
                if (ixj > i) {
                    unsigned long long a = key[i], c = key[ixj];
                    bool up = ((i & k) == 0);
                    if ((a > c) == up) { key[i] = c; key[ixj] = a; }
                }
            }
            __syncthreads();
        }

    __shared__ int sidx[256];
    if (t < 256) sidx[t] = (t < KK) ? (int)(key[t] & 0xFFFFFFFFull) : 0x7FFFFFFF;
    __syncthreads();
    for (int k = 2; k <= 256; k <<= 1)
        for (int j = k >> 1; j > 0; j >>= 1) {
            if (t < 256) {
                int i = t, ixj = i ^ j;
                if (ixj > i) {
                    int a = sidx[i], c = sidx[ixj];
                    bool up = ((i & k) == 0);
                    if ((a > c) == up) { sidx[i] = c; sidx[ixj] = a; }
                }
            }
            __syncthreads();
        }

    if (t < KK) {
        topidx[b * KK + t] = sidx[t];
        out[O_TOPIDX + b * KK + t] = (float)sidx[t];
    }
    if (t == 0) {
        int len = (int)ceilf((float)seqlen[b] * 0.4f);
        splen[b] = len;
        out[O_SPLEN + b] = (float)len;
    }
}

__global__ void gather_kernel(const float* __restrict__ span_vecs,
                              const int* __restrict__ span_begin,
                              const int* __restrict__ span_end,
                              const int* __restrict__ topidx,
                              float* __restrict__ out)
{
    int blk = blockIdx.x;
    int b = blk / KK, k = blk % KK;
    int idx = topidx[b * KK + k];
    const float* src = span_vecs + ((size_t)b * TL + idx) * DD;
    float* dst = out + O_FVECS + ((size_t)b * KK + k) * DD;
    for (int i = threadIdx.x; i < DD; i += 256) dst[i] = src[i];
    if (threadIdx.x == 0) {
        int g = b * TL + idx;
        out[O_FSCORE + b * KK + k] = out[O_PSCORE + g];
        out[O_FBEGIN + b * KK + k] = (float)span_begin[g];
        out[O_FEND   + b * KK + k] = (float)span_end[g];
    }
}

__global__ void mask_kernel(const int* __restrict__ splen, float* __restrict__ out)
{
    int i = blockIdx.x * blockDim.x + threadIdx.x;
    const int per = KK * KK;
    if (i >= BB * per) return;
    int b = i / per, r = i % per;
    int ii = r / KK, jj = r % KK;
    int len = splen[b];
    float v = (ii < len && jj < len) ? 1.0f : 0.0f;
    out[O_SQMASK + i] = v;
    out[O_TRMASK + i] = (jj <= ii) ? v : 0.0f;
}

// ---------------------------------------------------------------------------
extern "C" void kernel_launch(void* const* d_in, const int* in_sizes, int n_in,
                              void* d_out, int out_size)
{
    const float* span_vecs  = (const float*)d_in[0];
    const float* span_mask  = (const float*)d_in[1];
    const int*   span_begin = (const int*)  d_in[2];
    const int*   span_end   = (const int*)  d_in[3];
    const int*   seqlen     = (const int*)  d_in[4];
    const float* W1 = (const float*)d_in[5];
    const float* b1 = (const float*)d_in[6];
    const float* W2 = (const float*)d_in[7];
    const float* b2 = (const float*)d_in[8];
    const float* W3 = (const float*)d_in[9];
    const float* b3 = (const float*)d_in[10];
    float* out = (float*)d_out;

    __nv_bfloat16 *xhi, *xlo, *h1hi, *h1lo, *w1thi, *w1tlo, *w2thi, *w2tlo;
    float* spart; int *topidx, *splen;
    cudaGetSymbolAddress((void**)&xhi,   g_xhi);
    cudaGetSymbolAddress((void**)&xlo,   g_xlo);
    cudaGetSymbolAddress((void**)&h1hi,  g_h1hi);
    cudaGetSymbolAddress((void**)&h1lo,  g_h1lo);
    cudaGetSymbolAddress((void**)&w1thi, g_w1thi);
    cudaGetSymbolAddress((void**)&w1tlo, g_w1tlo);
    cudaGetSymbolAddress((void**)&w2thi, g_w2thi);
    cudaGetSymbolAddress((void**)&w2tlo, g_w2tlo);
    cudaGetSymbolAddress((void**)&spart, g_spart);
    cudaGetSymbolAddress((void**)&topidx, g_topidx);
    cudaGetSymbolAddress((void**)&splen,  g_spanlen);

    cudaFuncSetAttribute(gemm3_mma<1>, cudaFuncAttributeMaxDynamicSharedMemorySize, GEMM_SMEM);
    cudaFuncSetAttribute(gemm3_mma<2>, cudaFuncAttributeMaxDynamicSharedMemorySize, GEMM_SMEM);
    cudaFuncSetAttribute(topk_kernel, cudaFuncAttributeMaxDynamicSharedMemorySize, 65536);

    // 1) split inputs + weights into hi/lo bf16 (WT is [N][K], K-major)
    {
        size_t n4 = (size_t)MM * DD / 4;
        split_kernel<<<(unsigned)((n4 + 255) / 256), 256>>>((const float4*)span_vecs, xhi, xlo, n4);
    }
    {
        size_t n = (size_t)DD * HH;
        transpose_split<<<(unsigned)((n + 255) / 256), 256>>>(W1, w1thi, w1tlo, DD, HH);
    }
    {
        size_t n = (size_t)HH * HH;
        transpose_split<<<(unsigned)((n + 255) / 256), 256>>>(W2, w2thi, w2tlo, HH, HH);
    }

    // 2) GEMM1: relu(x @ W1 + b1) -> h1 (split bf16 hi/lo)
    {
        dim3 grid(HH / GBN, MM / GBM);   // (8, 240)
        gemm3_mma<1><<<grid, 256, GEMM_SMEM>>>(xhi, xlo, w1thi, w1tlo, b1,
                                               nullptr, nullptr, h1hi, h1lo, MM, HH, DD);
    }
    // 3) GEMM2 + fused W3 GEMV -> score partials (h2 never materialized)
    {
        dim3 grid(HH / GBN, MM / GBM);
        gemm3_mma<2><<<grid, 256, GEMM_SMEM>>>(h1hi, h1lo, w2thi, w2tlo, b2,
                                               W3, spart, nullptr, nullptr, MM, HH, HH);
    }

    // 4) finish scores + penalty
    score_finish<<<(MM + 255) / 256, 256>>>(spart, b3, span_mask, out);

    // 5) top-K per batch
    topk_kernel<<<BB, 1024, 65536>>>(out, seqlen, out, topidx, splen);

    // 6) gathers
    gather_kernel<<<BB * KK, 256>>>(span_vecs, span_begin, span_end, topidx, out);

    // 7) masks
    {
        int n = BB * KK * KK;
        mask_kernel<<<(n + 255) / 256, 256>>>(splen, out);
    }
}

// round 7
// speedup vs baseline: 3.5360x; 1.1400x over previous
#include <cuda_runtime.h>
#include <cuda_bf16.h>
#include <cstdint>

// ---------------------------------------------------------------------------
// MentionPrunerSpanBert: B=4, T=512, L=15, D=2048, H=1024, K=205
// R6: (a) two-phase parallel top-k (32-block segment sort -> 4-block merge),
//     (b) GEMM prefetch moved between compute halves so MMAs restart
//         immediately after each barrier.
// ---------------------------------------------------------------------------

#define BB   4
#define TT   512
#define LL   15
#define DD   2048
#define HH   1024
#define KK   205
#define TL   (TT * LL)          // 7680
#define MM   (BB * TL)          // 30720
#define NPART 8
#define NSEG 8
#define SEGLEN (TL / NSEG)      // 960

#define O_PSCORE 0
#define O_TOPIDX (O_PSCORE + MM)
#define O_FVECS  (O_TOPIDX + BB * KK)
#define O_FSCORE (O_FVECS  + (size_t)BB * KK * DD)
#define O_FBEGIN (O_FSCORE + BB * KK)
#define O_FEND   (O_FBEGIN + BB * KK)
#define O_SPLEN  (O_FEND   + BB * KK)
#define O_SQMASK (O_SPLEN  + BB)
#define O_TRMASK (O_SQMASK + BB * KK * KK)

// ---------------- device scratch (no allocations allowed) -------------------
__device__ __nv_bfloat16 g_xhi[(size_t)MM * DD];
__device__ __nv_bfloat16 g_xlo[(size_t)MM * DD];
__device__ __nv_bfloat16 g_h1hi[(size_t)MM * HH];
__device__ __nv_bfloat16 g_h1lo[(size_t)MM * HH];
__device__ __nv_bfloat16 g_w1thi[(size_t)HH * DD];
__device__ __nv_bfloat16 g_w1tlo[(size_t)HH * DD];
__device__ __nv_bfloat16 g_w2thi[(size_t)HH * HH];
__device__ __nv_bfloat16 g_w2tlo[(size_t)HH * HH];
__device__ float g_spart[(size_t)MM * NPART];
__device__ unsigned long long g_cand[BB * NSEG * KK];
__device__ int   g_topidx[BB * KK];
__device__ int   g_spanlen[BB];

// ---------------- PTX helpers (all arch-agnostic, sm_80+) -------------------
__device__ __forceinline__ uint32_t smem_u32_of(const void* p) {
    uint32_t a;
    asm("{ .reg .u64 t; cvta.to.shared.u64 t, %1; cvt.u32.u64 %0, t; }" : "=r"(a) : "l"(p));
    return a;
}
#define CP16(dst, src) \
    asm volatile("cp.async.cg.shared.global [%0], [%1], 16;" :: "r"((uint32_t)(dst)), "l"(src))
#define CP_COMMIT() asm volatile("cp.async.commit_group;" ::: "memory")
#define CP_WAIT(n)  asm volatile("cp.async.wait_group %0;" :: "n"(n) : "memory")

#define LDSM_X4(R0, R1, R2, R3, addr) \
    asm volatile("ldmatrix.sync.aligned.m8n8.x4.shared.b16 {%0,%1,%2,%3}, [%4];" \
        : "=r"(R0), "=r"(R1), "=r"(R2), "=r"(R3) : "r"(addr))

#define MMA_BF16(D, A, B0, B1) \
    asm volatile("mma.sync.aligned.m16n8k16.row.col.f32.bf16.bf16.f32 " \
        "{%0,%1,%2,%3}, {%4,%5,%6,%7}, {%8,%9}, {%0,%1,%2,%3};" \
        : "+f"((D)[0]), "+f"((D)[1]), "+f"((D)[2]), "+f"((D)[3]) \
        : "r"((A)[0]), "r"((A)[1]), "r"((A)[2]), "r"((A)[3]), "r"(B0), "r"(B1))

__device__ __forceinline__ uint32_t swz(int row, int chunk) {
    return (uint32_t)(row * 64 + (((chunk) ^ ((row >> 1) & 3)) & 3) * 16);
}

__device__ __forceinline__ unsigned long long score_key(float s, int idx) {
    unsigned u = __float_as_uint(s);
    u = (u & 0x80000000u) ? ~u : (u | 0x80000000u);
    return ((unsigned long long)(~u) << 32) | (unsigned)idx;
}

// ---------------------------------------------------------------------------
// Split / transpose-split preprocessing
// ---------------------------------------------------------------------------
__global__ void split_kernel(const float4* __restrict__ x,
                             __nv_bfloat16* __restrict__ hi,
                             __nv_bfloat16* __restrict__ lo, size_t n4)
{
    size_t i = (size_t)blockIdx.x * blockDim.x + threadIdx.x;
    if (i >= n4) return;
    float4 v = x[i];
    float vv[4] = {v.x, v.y, v.z, v.w};
    __nv_bfloat16 h[4], l[4];
#pragma unroll
    for (int k = 0; k < 4; k++) {
        h[k] = __float2bfloat16(vv[k]);
        l[k] = __float2bfloat16(vv[k] - __bfloat162float(h[k]));
    }
    __nv_bfloat162 h01, h23, l01, l23;
    h01.x = h[0]; h01.y = h[1]; h23.x = h[2]; h23.y = h[3];
    l01.x = l[0]; l01.y = l[1]; l23.x = l[2]; l23.y = l[3];
    __nv_bfloat162* hp = reinterpret_cast<__nv_bfloat162*>(hi) + 2 * i;
    __nv_bfloat162* lp = reinterpret_cast<__nv_bfloat162*>(lo) + 2 * i;
    hp[0] = h01; hp[1] = h23;
    lp[0] = l01; lp[1] = l23;
}

__global__ void transpose_split(const float* __restrict__ W,
                                __nv_bfloat16* __restrict__ Thi,
                                __nv_bfloat16* __restrict__ Tlo, int Kd, int N)
{
    size_t tid = (size_t)blockIdx.x * blockDim.x + threadIdx.x;
    if (tid >= (size_t)Kd * N) return;
    int k = (int)(tid % Kd);
    int n = (int)(tid / Kd);
    float v = W[(size_t)k * N + n];
    __nv_bfloat16 h = __float2bfloat16(v);
    Thi[tid] = h;
    Tlo[tid] = __float2bfloat16(v - __bfloat162float(h));
}

// ---------------------------------------------------------------------------
// Split-bf16 HMMA GEMM, tile 128x128, BK=32, 256 thr (4m x 2n warps),
// 3-stage cp.async pipeline, swizzled smem, one sync/chunk, 2 CTAs/SM.
// Prefetch issued between the two k16 compute halves (MMAs restart fast).
// ---------------------------------------------------------------------------
#define GBM 128
#define GBN 128
#define GBK 32
#define SM_AH 0
#define SM_AL 8192
#define SM_BH 16384
#define SM_BL 24576
#define STAGE_SZ 32768
#define NSTAGE 3
#define GEMM_SMEM (NSTAGE * STAGE_SZ)

template <int MODE>
__global__ __launch_bounds__(256, 2)
void gemm3_mma(const __nv_bfloat16* __restrict__ Ahi, const __nv_bfloat16* __restrict__ Alo,
               const __nv_bfloat16* __restrict__ Bhi, const __nv_bfloat16* __restrict__ Blo,
               const float* __restrict__ bias,
               const float* __restrict__ W3,
               float* __restrict__ spart,
               __nv_bfloat16* __restrict__ Chi, __nv_bfloat16* __restrict__ Clo,
               int M, int N, int Kd)
{
    extern __shared__ char smem[];
    const uint32_t sb = smem_u32_of(smem);
    const int t = threadIdx.x;
    const int lane = t & 31;
    const int wid = t >> 5;
    const int wm = wid & 3;
    const int wn = wid >> 2;
    const int mBase = blockIdx.y * GBM;
    const int nBase = blockIdx.x * GBN;
    const int NC = Kd / GBK;

    float acc[2][8][4];
#pragma unroll
    for (int mi = 0; mi < 2; mi++)
#pragma unroll
        for (int ni = 0; ni < 8; ni++)
#pragma unroll
            for (int j = 0; j < 4; j++) acc[mi][ni][j] = 0.0f;

    auto load_stage = [&](int cidx, int buf) {
        const size_t ko = (size_t)cidx * GBK;
        const uint32_t stg = sb + buf * STAGE_SZ;
#pragma unroll
        for (int p = 0; p < 2; p++) {
            const int idx = t + p * 256;
            const int row = idx >> 2;
            const int c16 = idx & 3;
            const uint32_t doff = swz(row, c16);
            const size_t aoff = (size_t)(mBase + row) * Kd + ko + c16 * 8;
            const size_t boff = (size_t)(nBase + row) * Kd + ko + c16 * 8;
            CP16(stg + SM_AH + doff, Ahi + aoff);
            CP16(stg + SM_AL + doff, Alo + aoff);
            CP16(stg + SM_BH + doff, Bhi + boff);
            CP16(stg + SM_BL + doff, Blo + boff);
        }
        CP_COMMIT();
    };

    const int ar = lane & 15, ac = lane >> 4;
    const int br = lane & 7,  bblk = lane >> 3;

    auto compute_half = [&](uint32_t stg, int kk2) {
        uint32_t ah[2][4], al[2][4];
#pragma unroll
        for (int mi = 0; mi < 2; mi++) {
            const int rowA = wm * 32 + mi * 16 + ar;
            const uint32_t ra = swz(rowA, kk2 * 2 + ac);
            LDSM_X4(ah[mi][0], ah[mi][1], ah[mi][2], ah[mi][3], stg + SM_AH + ra);
            LDSM_X4(al[mi][0], al[mi][1], al[mi][2], al[mi][3], stg + SM_AL + ra);
        }
        uint32_t bf[8][2];
#pragma unroll
        for (int nj = 0; nj < 4; nj++) {
            const int rowB = wn * 64 + nj * 16 + (bblk >> 1) * 8 + br;
            const uint32_t rb = swz(rowB, kk2 * 2 + (bblk & 1));
            LDSM_X4(bf[2*nj][0], bf[2*nj][1], bf[2*nj+1][0], bf[2*nj+1][1], stg + SM_BH + rb);
        }
#pragma unroll
        for (int mi = 0; mi < 2; mi++)
#pragma unroll
            for (int ni = 0; ni < 8; ni++) {
                MMA_BF16(acc[mi][ni], ah[mi], bf[ni][0], bf[ni][1]);
                MMA_BF16(acc[mi][ni], al[mi], bf[ni][0], bf[ni][1]);
            }
#pragma unroll
        for (int nj = 0; nj < 4; nj++) {
            const int rowB = wn * 64 + nj * 16 + (bblk >> 1) * 8 + br;
            const uint32_t rb = swz(rowB, kk2 * 2 + (bblk & 1));
            LDSM_X4(bf[2*nj][0], bf[2*nj][1], bf[2*nj+1][0], bf[2*nj+1][1], stg + SM_BL + rb);
        }
#pragma unroll
        for (int mi = 0; mi < 2; mi++)
#pragma unroll
            for (int ni = 0; ni < 8; ni++)
                MMA_BF16(acc[mi][ni], ah[mi], bf[ni][0], bf[ni][1]);
    };

    load_stage(0, 0);
    load_stage(1, 1);

#pragma unroll 1
    for (int c = 0; c < NC; c++) {
        const int buf = c % NSTAGE;
        if (c < NC - 1) CP_WAIT(1); else CP_WAIT(0);
        __syncthreads();
        const uint32_t stg = sb + buf * STAGE_SZ;
        compute_half(stg, 0);
        if (c + 2 < NC) load_stage(c + 2, (c + 2) % NSTAGE);   // prefetch mid-chunk
        compute_half(stg, 1);
    }

    // ---- epilogue ----
    const int r0 = lane >> 2;
    const int c0 = (lane & 3) << 1;

    if (MODE == 1) {
#pragma unroll
        for (int mi = 0; mi < 2; mi++) {
            const int rowA = mBase + wm * 32 + mi * 16 + r0;
#pragma unroll
            for (int ni = 0; ni < 8; ni++) {
                const int col = nBase + wn * 64 + ni * 8 + c0;
                const float bv0 = bias[col], bv1 = bias[col + 1];
                float v0 = acc[mi][ni][0] + bv0;  v0 = v0 > 0.0f ? v0 : 0.0f;
                float v1 = acc[mi][ni][1] + bv1;  v1 = v1 > 0.0f ? v1 : 0.0f;
                float v2 = acc[mi][ni][2] + bv0;  v2 = v2 > 0.0f ? v2 : 0.0f;
                float v3 = acc[mi][ni][3] + bv1;  v3 = v3 > 0.0f ? v3 : 0.0f;
                __nv_bfloat16 h0 = __float2bfloat16(v0), h1 = __float2bfloat16(v1);
                __nv_bfloat16 h2 = __float2bfloat16(v2), h3 = __float2bfloat16(v3);
                __nv_bfloat162 hh, ll;
                hh.x = h0; hh.y = h1;
                ll.x = __float2bfloat16(v0 - __bfloat162float(h0));
                ll.y = __float2bfloat16(v1 - __bfloat162float(h1));
                *reinterpret_cast<__nv_bfloat162*>(Chi + (size_t)rowA * N + col) = hh;
                *reinterpret_cast<__nv_bfloat162*>(Clo + (size_t)rowA * N + col) = ll;
                hh.x = h2; hh.y = h3;
                ll.x = __float2bfloat16(v2 - __bfloat162float(h2));
                ll.y = __float2bfloat16(v3 - __bfloat162float(h3));
                *reinterpret_cast<__nv_bfloat162*>(Chi + (size_t)(rowA + 8) * N + col) = hh;
                *reinterpret_cast<__nv_bfloat162*>(Clo + (size_t)(rowA + 8) * N + col) = ll;
            }
        }
    } else {
        float ps[2][2] = {{0.0f, 0.0f}, {0.0f, 0.0f}};
#pragma unroll
        for (int mi = 0; mi < 2; mi++) {
#pragma unroll
            for (int ni = 0; ni < 8; ni++) {
                const int col = nBase + wn * 64 + ni * 8 + c0;
                const float bv0 = bias[col], bv1 = bias[col + 1];
                const float w0 = W3[col], w1 = W3[col + 1];
                float v0 = acc[mi][ni][0] + bv0;  v0 = v0 > 0.0f ? v0 : 0.0f;
                float v1 = acc[mi][ni][1] + bv1;  v1 = v1 > 0.0f ? v1 : 0.0f;
                float v2 = acc[mi][ni][2] + bv0;  v2 = v2 > 0.0f ? v2 : 0.0f;
                float v3 = acc[mi][ni][3] + bv1;  v3 = v3 > 0.0f ? v3 : 0.0f;
                ps[mi][0] = fmaf(v0, w0, fmaf(v1, w1, ps[mi][0]));
                ps[mi][1] = fmaf(v2, w0, fmaf(v3, w1, ps[mi][1]));
            }
#pragma unroll
            for (int o = 1; o <= 2; o <<= 1) {
                ps[mi][0] += __shfl_xor_sync(0xffffffffu, ps[mi][0], o);
                ps[mi][1] += __shfl_xor_sync(0xffffffffu, ps[mi][1], o);
            }
        }
        float* pssum = reinterpret_cast<float*>(smem);
        __syncthreads();
        if ((lane & 3) == 0) {
#pragma unroll
            for (int mi = 0; mi < 2; mi++) {
                int lr = wm * 32 + mi * 16 + r0;
                pssum[(lr)     * 2 + wn] = ps[mi][0];
                pssum[(lr + 8) * 2 + wn] = ps[mi][1];
            }
        }
        __syncthreads();
        if (t < 128) {
            float s = pssum[t * 2] + pssum[t * 2 + 1];
            spart[(size_t)(mBase + t) * NPART + blockIdx.x] = s;
        }
    }
}

// ---------------------------------------------------------------------------
__global__ void score_finish(const float* __restrict__ spart,
                             const float* __restrict__ b3,
                             const float* __restrict__ mask,
                             float* __restrict__ out)
{
    int row = blockIdx.x * blockDim.x + threadIdx.x;
    if (row >= MM) return;
    const float* p = spart + (size_t)row * NPART;
    float s = b3[0];
#pragma unroll
    for (int j = 0; j < NPART; j++) s += p[j];
    out[O_PSCORE + row] = s - (1.0f - mask[row]) * 10000.0f;
}

// ---------------------------------------------------------------------------
// Top-K phase A: 32 blocks (batch x 8 segments of 960), each sorts 1024 keys
// and emits its local top-205. Global top-205 is a subset of the union.
// ---------------------------------------------------------------------------
__global__ void topk_phaseA(const float* __restrict__ out_ro,
                            unsigned long long* __restrict__ cand)
{
    __shared__ unsigned long long key[1024];
    const int b = blockIdx.x >> 3;
    const int seg = blockIdx.x & 7;
    const int t = threadIdx.x;          // 512
    const int base = seg * SEGLEN;

    for (int i = t; i < 1024; i += 512) {
        unsigned long long kv = 0xFFFFFFFFFFFFFFFFull;
        if (i < SEGLEN) {
            int gi = base + i;
            kv = score_key(out_ro[O_PSCORE + b * TL + gi], gi);
        }
        key[i] = kv;
    }
    __syncthreads();

    for (int k = 2; k <= 1024; k <<= 1)
        for (int j = k >> 1; j > 0; j >>= 1) {
            for (int i = t; i < 1024; i += 512) {
                int ixj = i ^ j;
                if (ixj > i) {
                    unsigned long long a = key[i], c = key[ixj];
                    bool up = ((i & k) == 0);
                    if ((a > c) == up) { key[i] = c; key[ixj] = a; }
                }
            }
            __syncthreads();
        }

    if (t < KK) cand[(b * NSEG + seg) * KK + t] = key[t];
}

// ---------------------------------------------------------------------------
// Top-K phase B: 4 blocks, sort the 1640 candidates (padded to 2048), take
// top-205, sort indices ascending, write outputs.
// ---------------------------------------------------------------------------
__global__ void topk_phaseB(const unsigned long long* __restrict__ cand,
                            const int* __restrict__ seqlen,
                            float* __restrict__ out,
                            int* __restrict__ topidx,
                            int* __restrict__ splen)
{
    __shared__ unsigned long long key[2048];
    const int b = blockIdx.x;
    const int t = threadIdx.x;          // 1024

    for (int i = t; i < 2048; i += 1024)
        key[i] = (i < NSEG * KK) ? cand[b * NSEG * KK + i] : 0xFFFFFFFFFFFFFFFFull;
    __syncthreads();

    for (int k = 2; k <= 2048; k <<= 1)
        for (int j = k >> 1; j > 0; j >>= 1) {
            for (int i = t; i < 2048; i += 1024) {
                int ixj = i ^ j;
                if (ixj > i) {
                    unsigned long long a = key[i], c = key[ixj];
                    bool up = ((i & k) == 0);
                    if ((a > c) == up) { key[i] = c; key[ixj] = a; }
                }
            }
            __syncthreads();
        }

    __shared__ int sidx[256];
    if (t < 256) sidx[t] = (t < KK) ? (int)(key[t] & 0xFFFFFFFFull) : 0x7FFFFFFF;
    __syncthreads();
    for (int k = 2; k <= 256; k <<= 1)
        for (int j = k >> 1; j > 0; j >>= 1) {
            if (t < 256) {
                int i = t, ixj = i ^ j;
                if (ixj > i) {
                    int a = sidx[i], c = sidx[ixj];
                    bool up = ((i & k) == 0);
                    if ((a > c) == up) { sidx[i] = c; sidx[ixj] = a; }
                }
            }
            __syncthreads();
        }

    if (t < KK) {
        topidx[b * KK + t] = sidx[t];
        out[O_TOPIDX + b * KK + t] = (float)sidx[t];
    }
    if (t == 0) {
        int len = (int)ceilf((float)seqlen[b] * 0.4f);
        splen[b] = len;
        out[O_SPLEN + b] = (float)len;
    }
}

__global__ void gather_kernel(const float* __restrict__ span_vecs,
                              const int* __restrict__ span_begin,
                              const int* __restrict__ span_end,
                              const int* __restrict__ topidx,
                              float* __restrict__ out)
{
    int blk = blockIdx.x;
    int b = blk / KK, k = blk % KK;
    int idx = topidx[b * KK + k];
    const float* src = span_vecs + ((size_t)b * TL + idx) * DD;
    float* dst = out + O_FVECS + ((size_t)b * KK + k) * DD;
    for (int i = threadIdx.x; i < DD; i += 256) dst[i] = src[i];
    if (threadIdx.x == 0) {
        int g = b * TL + idx;
        out[O_FSCORE + b * KK + k] = out[O_PSCORE + g];
        out[O_FBEGIN + b * KK + k] = (float)span_begin[g];
        out[O_FEND   + b * KK + k] = (float)span_end[g];
    }
}

__global__ void mask_kernel(const int* __restrict__ splen, float* __restrict__ out)
{
    int i = blockIdx.x * blockDim.x + threadIdx.x;
    const int per = KK * KK;
    if (i >= BB * per) return;
    int b = i / per, r = i % per;
    int ii = r / KK, jj = r % KK;
    int len = splen[b];
    float v = (ii < len && jj < len) ? 1.0f : 0.0f;
    out[O_SQMASK + i] = v;
    out[O_TRMASK + i] = (jj <= ii) ? v : 0.0f;
}

// ---------------------------------------------------------------------------
extern "C" void kernel_launch(void* const* d_in, const int* in_sizes, int n_in,
                              void* d_out, int out_size)
{
    const float* span_vecs  = (const float*)d_in[0];
    const float* span_mask  = (const float*)d_in[1];
    const int*   span_begin = (const int*)  d_in[2];
    const int*   span_end   = (const int*)  d_in[3];
    const int*   seqlen     = (const int*)  d_in[4];
    const float* W1 = (const float*)d_in[5];
    const float* b1 = (const float*)d_in[6];
    const float* W2 = (const float*)d_in[7];
    const float* b2 = (const float*)d_in[8];
    const float* W3 = (const float*)d_in[9];
    const float* b3 = (const float*)d_in[10];
    float* out = (float*)d_out;

    __nv_bfloat16 *xhi, *xlo, *h1hi, *h1lo, *w1thi, *w1tlo, *w2thi, *w2tlo;
    float* spart; unsigned long long* cand; int *topidx, *splen;
    cudaGetSymbolAddress((void**)&xhi,   g_xhi);
    cudaGetSymbolAddress((void**)&xlo,   g_xlo);
    cudaGetSymbolAddress((void**)&h1hi,  g_h1hi);
    cudaGetSymbolAddress((void**)&h1lo,  g_h1lo);
    cudaGetSymbolAddress((void**)&w1thi, g_w1thi);
    cudaGetSymbolAddress((void**)&w1tlo, g_w1tlo);
    cudaGetSymbolAddress((void**)&w2thi, g_w2thi);
    cudaGetSymbolAddress((void**)&w2tlo, g_w2tlo);
    cudaGetSymbolAddress((void**)&spart, g_spart);
    cudaGetSymbolAddress((void**)&cand,  g_cand);
    cudaGetSymbolAddress((void**)&topidx, g_topidx);
    cudaGetSymbolAddress((void**)&splen,  g_spanlen);

    cudaFuncSetAttribute(gemm3_mma<1>, cudaFuncAttributeMaxDynamicSharedMemorySize, GEMM_SMEM);
    cudaFuncSetAttribute(gemm3_mma<2>, cudaFuncAttributeMaxDynamicSharedMemorySize, GEMM_SMEM);

    // 1) split inputs + weights into hi/lo bf16 (WT is [N][K], K-major)
    {
        size_t n4 = (size_t)MM * DD / 4;
        split_kernel<<<(unsigned)((n4 + 255) / 256), 256>>>((const float4*)span_vecs, xhi, xlo, n4);
    }
    {
        size_t n = (size_t)DD * HH;
        transpose_split<<<(unsigned)((n + 255) / 256), 256>>>(W1, w1thi, w1tlo, DD, HH);
    }
    {
        size_t n = (size_t)HH * HH;
        transpose_split<<<(unsigned)((n + 255) / 256), 256>>>(W2, w2thi, w2tlo, HH, HH);
    }

    // 2) GEMM1: relu(x @ W1 + b1) -> h1 (split bf16 hi/lo)
    {
        dim3 grid(HH / GBN, MM / GBM);   // (8, 240)
        gemm3_mma<1><<<grid, 256, GEMM_SMEM>>>(xhi, xlo, w1thi, w1tlo, b1,
                                               nullptr, nullptr, h1hi, h1lo, MM, HH, DD);
    }
    // 3) GEMM2 + fused W3 GEMV -> score partials (h2 never materialized)
    {
        dim3 grid(HH / GBN, MM / GBM);
        gemm3_mma<2><<<grid, 256, GEMM_SMEM>>>(h1hi, h1lo, w2thi, w2tlo, b2,
                                               W3, spart, nullptr, nullptr, MM, HH, HH);
    }

    // 4) finish scores + penalty
    score_finish<<<(MM + 255) / 256, 256>>>(spart, b3, span_mask, out);

    // 5) top-K per batch: two-phase (32 blocks, then 4 blocks)
    topk_phaseA<<<BB * NSEG, 512>>>(out, cand);
    topk_phaseB<<<BB, 1024>>>(cand, seqlen, out, topidx, splen);

    // 6) gathers
    gather_kernel<<<BB * KK, 256>>>(span_vecs, span_begin, span_end, topidx, out);

    // 7) masks
    {
        int n = BB * KK * KK;
        mask_kernel<<<(n + 255) / 256, 256>>>(splen, out);
    }
}